// round 13
// baseline (speedup 1.0000x reference)
#include <cuda_runtime.h>
#include <cuda_fp16.h>
#include <cstdint>

// ---------------- problem constants ----------------
#define B_      2
#define S_      4096
#define H_      2048
#define NH_     16
#define NKV_    4
#define D_      128
#define BS_     64
#define KB_     (S_ / BS_)
#define NGLOB_  4
#define NLOCAL_ 8
#define NSEL_   (NGLOB_ + NLOCAL_)
#define STRIDE_ 16
#define NTOK_   (B_ * S_)       // 8192
#define QDIM_   (NH_ * D_)      // 2048
#define KVDIM_  (NKV_ * D_)     // 512
#define SCALE_  0.088388347648318447f
#define NEG_    (-1000000000.0f)

// ---------------- scratch ---------------------------------------------------
__device__ float  g_q[(size_t)NTOK_ * QDIM_];
__device__ float  g_k[(size_t)NTOK_ * KVDIM_];
__device__ float  g_v[(size_t)NTOK_ * KVDIM_];
__device__ __half g_attn[(size_t)NTOK_ * QDIM_];      // attention out (fp16)
__device__ __half g_xh[(size_t)NTOK_ * H_];           // X in fp16
// weights fp16: [Wq 4M][Wk 1M][Wv 1M][Wo 4M] halves
#define WQ_OFF_ 0
#define WK_OFF_ ((size_t)QDIM_ * H_)
#define WV_OFF_ (WK_OFF_ + (size_t)KVDIM_ * H_)
#define WO_OFF_ (WV_OFF_ + (size_t)KVDIM_ * H_)
#define WH_HALVES_ (WO_OFF_ + (size_t)QDIM_ * H_)
__device__ __half g_wh[WH_HALVES_];

// ---------------- helpers ---------------------------------------------------
__device__ __forceinline__ uint32_t f2tf32(float x) {
    uint32_t u;
    asm("cvt.rna.tf32.f32 %0, %1;" : "=r"(u) : "f"(x));
    return u;
}
__device__ __forceinline__ void split_tf32(float x, uint32_t& hi, uint32_t& lo) {
    hi = f2tf32(x);
    lo = f2tf32(x - __uint_as_float(hi));
}
__device__ __forceinline__ void mma_tf32(float* c, const uint32_t* a, const uint32_t* b) {
    asm volatile(
        "mma.sync.aligned.m16n8k8.row.col.f32.tf32.tf32.f32 "
        "{%0,%1,%2,%3}, {%4,%5,%6,%7}, {%8,%9}, {%0,%1,%2,%3};\n"
        : "+f"(c[0]), "+f"(c[1]), "+f"(c[2]), "+f"(c[3])
        : "r"(a[0]), "r"(a[1]), "r"(a[2]), "r"(a[3]), "r"(b[0]), "r"(b[1]));
}
__device__ __forceinline__ void mma_f16_k16(float* c, const uint32_t* a, const uint32_t* b) {
    asm volatile(
        "mma.sync.aligned.m16n8k16.row.col.f32.f16.f16.f32 "
        "{%0,%1,%2,%3}, {%4,%5,%6,%7}, {%8,%9}, {%0,%1,%2,%3};\n"
        : "+f"(c[0]), "+f"(c[1]), "+f"(c[2]), "+f"(c[3])
        : "r"(a[0]), "r"(a[1]), "r"(a[2]), "r"(a[3]), "r"(b[0]), "r"(b[1]));
}
__device__ __forceinline__ void cp_async16(uint32_t saddr, const void* gptr) {
    asm volatile("cp.async.cg.shared.global [%0], [%1], 16;\n"
                 :: "r"(saddr), "l"(gptr));
}

// ---------------- merged fp32 -> fp16 conversion ----------------------------
#define CVT_X4_   (NTOK_ * (H_ / 4))
#define CVT_WQ4_  (QDIM_ * (H_ / 4))
#define CVT_WK4_  (KVDIM_ * (H_ / 4))
#define CVT_TOT4_ (CVT_X4_ + CVT_WQ4_ + 2 * CVT_WK4_ + CVT_WQ4_)

__global__ void cvt_all_kernel(const float* __restrict__ X,
                               const float* __restrict__ Wq,
                               const float* __restrict__ Wk,
                               const float* __restrict__ Wv,
                               const float* __restrict__ Wo)
{
    int i = blockIdx.x * blockDim.x + threadIdx.x;
    if (i >= CVT_TOT4_) return;

    const float4* src;
    uint2* dst;
    if (i < CVT_X4_) {
        src = (const float4*)X + i;
        dst = (uint2*)g_xh + i;
    } else if (i < CVT_X4_ + CVT_WQ4_) {
        int j = i - CVT_X4_;
        src = (const float4*)Wq + j;
        dst = (uint2*)(g_wh + WQ_OFF_) + j;
    } else if (i < CVT_X4_ + CVT_WQ4_ + CVT_WK4_) {
        int j = i - CVT_X4_ - CVT_WQ4_;
        src = (const float4*)Wk + j;
        dst = (uint2*)(g_wh + WK_OFF_) + j;
    } else if (i < CVT_X4_ + CVT_WQ4_ + 2 * CVT_WK4_) {
        int j = i - CVT_X4_ - CVT_WQ4_ - CVT_WK4_;
        src = (const float4*)Wv + j;
        dst = (uint2*)(g_wh + WV_OFF_) + j;
    } else {
        int j = i - CVT_X4_ - CVT_WQ4_ - 2 * CVT_WK4_;
        src = (const float4*)Wo + j;
        dst = (uint2*)(g_wh + WO_OFF_) + j;
    }
    float4 v = *src;
    __half2 h0 = __floats2half2_rn(v.x, v.y);
    __half2 h1 = __floats2half2_rn(v.z, v.w);
    uint2 o;
    o.x = *(uint32_t*)&h0;
    o.y = *(uint32_t*)&h1;
    *dst = o;
}

// ---------------- pipelined fp16 GEMM ---------------------------------------
#define BKH_  32
#define LDHW_ 20
#define GSTG_ 4
#define ST_WORDS_ (2 * 128 * LDHW_)
#define GSMEM_BYTES (GSTG_ * ST_WORDS_ * 4)      // 81920

__global__ void __launch_bounds__(256, 2)
gemm_f16_pipe(const __half* __restrict__ A, const __half* __restrict__ B,
              float* __restrict__ C0, float* __restrict__ C1,
              int Nsplit, int ldc, int K)
{
    extern __shared__ uint32_t smg[];

    const size_t bm = (size_t)blockIdx.y * 128;
    const size_t bn = (size_t)blockIdx.x * 128;
    const int t = threadIdx.x;
    const int lane = t & 31, warp = t >> 5;
    const int g  = lane >> 2, tg = lane & 3;
    const int wm = (warp >> 2) * 64;
    const int wn = (warp & 3) * 32;

    float acc[4][4][4];
#pragma unroll
    for (int mi = 0; mi < 4; mi++)
#pragma unroll
        for (int ni = 0; ni < 4; ni++)
#pragma unroll
            for (int c = 0; c < 4; c++) acc[mi][ni][c] = 0.0f;

    auto load_stage = [&](int s, int i) {
        uint32_t* as = smg + s * ST_WORDS_;
        uint32_t* bs = as + 128 * LDHW_;
        const int k0 = i * BKH_;
#pragma unroll
        for (int j = 0; j < 2; j++) {
            int idx = t + j * 256;
            int row = idx >> 2, c4 = idx & 3;
            uint32_t sa = (uint32_t)__cvta_generic_to_shared(&as[row * LDHW_ + c4 * 4]);
            cp_async16(sa, A + (bm + row) * (size_t)K + k0 + c4 * 8);
            uint32_t sb = (uint32_t)__cvta_generic_to_shared(&bs[row * LDHW_ + c4 * 4]);
            cp_async16(sb, B + (bn + row) * (size_t)K + k0 + c4 * 8);
        }
        asm volatile("cp.async.commit_group;\n");
    };

    auto compute_stage = [&](int s) {
        const uint32_t* as = smg + s * ST_WORDS_;
        const uint32_t* bs = as + 128 * LDHW_;
#pragma unroll
        for (int kk = 0; kk < 2; kk++) {
            const int kb = kk * 8;
            uint32_t a[4][4];
#pragma unroll
            for (int mi = 0; mi < 4; mi++) {
                const int m0 = wm + mi * 16;
                a[mi][0] = as[(m0 + g) * LDHW_ + kb + tg];
                a[mi][1] = as[(m0 + g + 8) * LDHW_ + kb + tg];
                a[mi][2] = as[(m0 + g) * LDHW_ + kb + tg + 4];
                a[mi][3] = as[(m0 + g + 8) * LDHW_ + kb + tg + 4];
            }
            uint32_t bf[4][2];
#pragma unroll
            for (int ni = 0; ni < 4; ni++) {
                const int n0 = wn + ni * 8;
                bf[ni][0] = bs[(n0 + g) * LDHW_ + kb + tg];
                bf[ni][1] = bs[(n0 + g) * LDHW_ + kb + tg + 4];
            }
#pragma unroll
            for (int mi = 0; mi < 4; mi++)
#pragma unroll
                for (int ni = 0; ni < 4; ni++)
                    mma_f16_k16(acc[mi][ni], a[mi], bf[ni]);
        }
    };

    const int niter = K / BKH_;
    load_stage(0, 0);
    load_stage(1, 1);
    load_stage(2, 2);

    for (int i = 0; i < niter - 1; i++) {
        asm volatile("cp.async.wait_group 2;\n" ::: "memory");
        __syncthreads();
        if (i + 3 < niter) load_stage((i + 3) % GSTG_, i + 3);
        compute_stage(i % GSTG_);
    }
    asm volatile("cp.async.wait_group 0;\n" ::: "memory");
    __syncthreads();
    compute_stage((niter - 1) % GSTG_);

    float* C = C0;
    int cb = (int)bn;
    if (cb >= Nsplit) { C = C1; cb -= Nsplit; }

#pragma unroll
    for (int mi = 0; mi < 4; mi++) {
        const size_t row = bm + wm + mi * 16 + g;
#pragma unroll
        for (int ni = 0; ni < 4; ni++) {
            const int col = cb + wn + ni * 8 + 2 * tg;
            float* cp0 = C + row * ldc + col;
            float* cp1 = cp0 + (size_t)8 * ldc;
            *(float2*)cp0 = make_float2(acc[mi][ni][0], acc[mi][ni][1]);
            *(float2*)cp1 = make_float2(acc[mi][ni][2], acc[mi][ni][3]);
        }
    }
}

// ---------------- RoPE (in-place on g_q, g_k) -------------------------------
__global__ void rope_kernel(const float* __restrict__ cosp,
                            const float* __restrict__ sinp)
{
    int idx = blockIdx.x * blockDim.x + threadIdx.x;
    const int total = NTOK_ * (NH_ + NKV_) * (D_ / 2);
    if (idx >= total) return;

    int d    = idx % (D_ / 2);
    int rest = idx / (D_ / 2);
    int h    = rest % (NH_ + NKV_);
    int tok  = rest / (NH_ + NKV_);

    float c1 = cosp[(size_t)tok * D_ + d];
    float s1 = sinp[(size_t)tok * D_ + d];
    float c2 = cosp[(size_t)tok * D_ + d + D_ / 2];
    float s2 = sinp[(size_t)tok * D_ + d + D_ / 2];

    float* buf;
    if (h < NH_) buf = g_q + (size_t)tok * QDIM_ + h * D_;
    else         buf = g_k + (size_t)tok * KVDIM_ + (h - NH_) * D_;

    float x1 = buf[d];
    float x2 = buf[d + D_ / 2];
    buf[d]           = x1 * c1 - x2 * s1;
    buf[d + D_ / 2]  = x2 * c2 + x1 * s2;
}

// ---------------- block-sparse attention (3xTF32, cp.async pipelined) -------
// smem: Qs[64][132] | Ks[64][132] (Ss[64][68] aliases Ks) | Vs[64][132] | stats
#define LDQ_   132
#define LDSS_  68
#define QS_OFF_   0
#define KS_OFF_   (64 * LDQ_)
#define VS_OFF_   (2 * 64 * LDQ_)
#define STAT_OFF_ (3 * 64 * LDQ_)
#define AT_SMEM_FLOATS (3 * 64 * LDQ_ + 128 + 128 + 3 * 64)
#define AT_SMEM_BYTES  (AT_SMEM_FLOATS * 4)      // 103168

__global__ void __launch_bounds__(256, 2)
attn_kernel()
{
    extern __shared__ float sm[];
    float* Qs   = sm + QS_OFF_;
    float* Ks   = sm + KS_OFF_;
    float* Ss   = sm + KS_OFF_;          // aliases Ks (K dead before P store)
    float* Vs   = sm + VS_OFF_;
    float* wmax = sm + STAT_OFF_;        // [2][64]
    float* wsum = wmax + 128;            // [2][64]
    float* rowm = wsum + 128;
    float* rowl = rowm + 64;
    float* rowf = rowl + 64;
    __shared__ int sel_s[NSEL_];
    __shared__ int keep_s[NSEL_];
    __shared__ int klist[NSEL_];
    __shared__ int kcnt;

    const int qid = blockIdx.x;
    const int h   = blockIdx.y;
    const int b   = blockIdx.z;
    const int t   = threadIdx.x;
    const int kvh = h / (NH_ / NKV_);

    const int warp = t >> 5, lane = t & 31;
    const int g  = lane >> 2;
    const int tg = lane & 3;
    const int wm  = (warp >> 1) * 16;
    const int nh  = warp & 1;
    const int wn  = nh * 32;
    const int wn2 = nh * 64;
    const int row0 = wm + g;
    const int row1 = wm + g + 8;

    // block selection + dedup, then compaction
    if (t < NSEL_) {
        int s;
        if (t < NGLOB_) { s = t * STRIDE_; if (s > KB_ - 1) s = KB_ - 1; }
        else            { int j = t - NGLOB_; s = qid - (NLOCAL_ - 1) + j;
                          s = s < 0 ? 0 : (s > KB_ - 1 ? KB_ - 1 : s); }
        bool valid = (s <= qid);
        bool dup = false;
        for (int jj = 0; jj < t; jj++) {
            int sj;
            if (jj < NGLOB_) { sj = jj * STRIDE_; if (sj > KB_ - 1) sj = KB_ - 1; }
            else             { int j2 = jj - NGLOB_; sj = qid - (NLOCAL_ - 1) + j2;
                               sj = sj < 0 ? 0 : (sj > KB_ - 1 ? KB_ - 1 : sj); }
            if (sj == s) dup = true;
        }
        sel_s[t]  = s;
        keep_s[t] = (valid && !dup) ? 1 : 0;
    }
    if (t < 64) { rowm[t] = -1e30f; rowl[t] = 0.0f; }
    __syncthreads();
    if (t == 0) {
        int c = 0;
        for (int j = 0; j < NSEL_; j++)
            if (keep_s[j]) klist[c++] = sel_s[j];
        kcnt = c;
    }
    __syncthreads();
    const int cnt = kcnt;

    // cp.async tile loader: 64 rows x 128 floats = 2048 16B chunks, 8/thread
    const float* kbase = g_k + ((size_t)(b * S_)) * KVDIM_ + kvh * D_;
    const float* vbase = g_v + ((size_t)(b * S_)) * KVDIM_ + kvh * D_;
    auto load_tile = [&](float* dstbuf, const float* src) {
#pragma unroll
        for (int j = 0; j < 8; j++) {
            int idx = t + j * 256;
            int r = idx >> 5, c16 = idx & 31;
            uint32_t d = (uint32_t)__cvta_generic_to_shared(&dstbuf[r * LDQ_ + c16 * 4]);
            cp_async16(d, src + (size_t)r * KVDIM_ + c16 * 4);
        }
        asm volatile("cp.async.commit_group;\n");
    };

    // prologue: prefetch K[0]
    load_tile(Ks, kbase + (size_t)klist[0] * BS_ * KVDIM_);

    // load Q block (plain loads; overlaps K prefetch)
    const float* qptr = g_q + ((size_t)(b * S_ + qid * BS_)) * QDIM_ + h * D_;
    for (int i4 = t; i4 < 64 * 32; i4 += 256) {
        int r = i4 >> 5, d4 = (i4 & 31) << 2;
        *(float4*)&Qs[r * LDQ_ + d4] = *(const float4*)(qptr + (size_t)r * QDIM_ + d4);
    }

    float o[8][4];
#pragma unroll
    for (int ni = 0; ni < 8; ni++)
#pragma unroll
        for (int c = 0; c < 4; c++) o[ni][c] = 0.0f;

    for (int bi = 0; bi < cnt; bi++) {
        const int kblk = klist[bi];
        const bool diag = (kblk == qid);

        // K[bi] ready; Qs also visible after this barrier
        asm volatile("cp.async.wait_group 0;\n" ::: "memory");
        __syncthreads();

        // start V[bi] load; it proceeds under S-mma + softmax
        load_tile(Vs, vbase + (size_t)kblk * BS_ * KVDIM_);

        // ---- S = Q @ K^T (3xTF32)
        float sacc[4][4];
#pragma unroll
        for (int ni = 0; ni < 4; ni++)
#pragma unroll
            for (int c = 0; c < 4; c++) sacc[ni][c] = 0.0f;

#pragma unroll
        for (int ks = 0; ks < 16; ks++) {
            const int kb = ks * 8;
            uint32_t ahi[4], alo[4];
            split_tf32(Qs[row0 * LDQ_ + kb + tg],     ahi[0], alo[0]);
            split_tf32(Qs[row1 * LDQ_ + kb + tg],     ahi[1], alo[1]);
            split_tf32(Qs[row0 * LDQ_ + kb + tg + 4], ahi[2], alo[2]);
            split_tf32(Qs[row1 * LDQ_ + kb + tg + 4], ahi[3], alo[3]);
#pragma unroll
            for (int ni = 0; ni < 4; ni++) {
                const int n = wn + ni * 8 + g;
                uint32_t bhi[2], blo[2];
                split_tf32(Ks[n * LDQ_ + kb + tg],     bhi[0], blo[0]);
                split_tf32(Ks[n * LDQ_ + kb + tg + 4], bhi[1], blo[1]);
                mma_tf32(sacc[ni], ahi, bhi);
                mma_tf32(sacc[ni], ahi, blo);
                mma_tf32(sacc[ni], alo, bhi);
            }
        }

        // ---- scale + mask + partial max
        float pm0 = -1e30f, pm1 = -1e30f;
#pragma unroll
        for (int ni = 0; ni < 4; ni++) {
            const int colb = wn + ni * 8 + 2 * tg;
#pragma unroll
            for (int c = 0; c < 4; c++) {
                const int col = colb + (c & 1);
                const int row = (c < 2) ? row0 : row1;
                float v = sacc[ni][c] * SCALE_;
                if (diag && col > row) v += NEG_;
                sacc[ni][c] = v;
                if (c < 2) pm0 = fmaxf(pm0, v);
                else       pm1 = fmaxf(pm1, v);
            }
        }
        pm0 = fmaxf(pm0, __shfl_xor_sync(0xffffffff, pm0, 1));
        pm0 = fmaxf(pm0, __shfl_xor_sync(0xffffffff, pm0, 2));
        pm1 = fmaxf(pm1, __shfl_xor_sync(0xffffffff, pm1, 1));
        pm1 = fmaxf(pm1, __shfl_xor_sync(0xffffffff, pm1, 2));
        if (tg == 0) {
            wmax[nh * 64 + row0] = pm0;
            wmax[nh * 64 + row1] = pm1;
        }
        __syncthreads();   // all warps done with Ks; Ss overwrite now safe

        float mx0 = fmaxf(fmaxf(wmax[row0], wmax[64 + row0]), rowm[row0]);
        float mx1 = fmaxf(fmaxf(wmax[row1], wmax[64 + row1]), rowm[row1]);
        float ps0 = 0.0f, ps1 = 0.0f;
#pragma unroll
        for (int ni = 0; ni < 4; ni++) {
#pragma unroll
            for (int c = 0; c < 4; c++) {
                float p = __expf(sacc[ni][c] - ((c < 2) ? mx0 : mx1));
                sacc[ni][c] = p;
                if (c < 2) ps0 += p; else ps1 += p;
            }
        }
        ps0 += __shfl_xor_sync(0xffffffff, ps0, 1);
        ps0 += __shfl_xor_sync(0xffffffff, ps0, 2);
        ps1 += __shfl_xor_sync(0xffffffff, ps1, 1);
        ps1 += __shfl_xor_sync(0xffffffff, ps1, 2);
        if (tg == 0) {
            wsum[nh * 64 + row0] = ps0;
            wsum[nh * 64 + row1] = ps1;
        }
        float mxt = 0.0f, ft = 0.0f;
        if (t < 64) {
            mxt = fmaxf(fmaxf(wmax[t], wmax[64 + t]), rowm[t]);
            ft  = __expf(rowm[t] - mxt);
            rowf[t] = ft;
        }
        __syncthreads();

        if (t < 64) {
            rowl[t] = rowl[t] * ft + wsum[t] + wsum[64 + t];
            rowm[t] = mxt;
        }

        // rescale O; store P into Ss (aliases Ks)
        {
            float f0 = rowf[row0], f1 = rowf[row1];
#pragma unroll
            for (int ni = 0; ni < 8; ni++) {
                o[ni][0] *= f0; o[ni][1] *= f0;
                o[ni][2] *= f1; o[ni][3] *= f1;
            }
        }
#pragma unroll
        for (int ni = 0; ni < 4; ni++) {
            const int colb = wn + ni * 8 + 2 * tg;
            *(float2*)&Ss[row0 * LDSS_ + colb] = make_float2(sacc[ni][0], sacc[ni][1]);
            *(float2*)&Ss[row1 * LDSS_ + colb] = make_float2(sacc[ni][2], sacc[ni][3]);
        }

        // V[bi] ready + P visible
        asm volatile("cp.async.wait_group 0;\n" ::: "memory");
        __syncthreads();

        // ---- O += P @ V (3xTF32)
#pragma unroll
        for (int ks = 0; ks < 8; ks++) {
            const int kb = ks * 8;
            uint32_t ahi[4], alo[4];
            split_tf32(Ss[row0 * LDSS_ + kb + tg],     ahi[0], alo[0]);
            split_tf32(Ss[row1 * LDSS_ + kb + tg],     ahi[1], alo[1]);
            split_tf32(Ss[row0 * LDSS_ + kb + tg + 4], ahi[2], alo[2]);
            split_tf32(Ss[row1 * LDSS_ + kb + tg + 4], ahi[3], alo[3]);
#pragma unroll
            for (int ni = 0; ni < 8; ni++) {
                const int n = wn2 + ni * 8 + g;
                uint32_t bhi[2], blo[2];
                split_tf32(Vs[(kb + tg) * LDQ_ + n],     bhi[0], blo[0]);
                split_tf32(Vs[(kb + tg + 4) * LDQ_ + n], bhi[1], blo[1]);
                mma_tf32(o[ni], ahi, bhi);
                mma_tf32(o[ni], ahi, blo);
                mma_tf32(o[ni], alo, bhi);
            }
        }
        __syncthreads();   // Ss/Vs reads complete

        // prefetch K[bi+1]; runs under loop bookkeeping + next top
        if (bi + 1 < cnt)
            load_tile(Ks, kbase + (size_t)klist[bi + 1] * BS_ * KVDIM_);
    }

    // finalize: divide by denom, write out as fp16 (feeds O projection)
    const float invl0 = 1.0f / rowl[row0];
    const float invl1 = 1.0f / rowl[row1];
    __half* ob0 = g_attn + ((size_t)(b * S_ + qid * BS_ + row0)) * QDIM_ + h * D_;
    __half* ob1 = g_attn + ((size_t)(b * S_ + qid * BS_ + row1)) * QDIM_ + h * D_;
#pragma unroll
    for (int ni = 0; ni < 8; ni++) {
        const int col = wn2 + ni * 8 + 2 * tg;
        __half2 h0 = __floats2half2_rn(o[ni][0] * invl0, o[ni][1] * invl0);
        __half2 h1 = __floats2half2_rn(o[ni][2] * invl1, o[ni][3] * invl1);
        *(__half2*)(ob0 + col) = h0;
        *(__half2*)(ob1 + col) = h1;
    }
}

// ---------------- host launcher ---------------------------------------------
extern "C" void kernel_launch(void* const* d_in, const int* in_sizes, int n_in,
                              void* d_out, int out_size)
{
    const float* X    = (const float*)d_in[0];
    const float* cosp = (const float*)d_in[1];
    const float* sinp = (const float*)d_in[2];
    const float* Wq   = (const float*)d_in[3];
    const float* Wk   = (const float*)d_in[4];
    const float* Wv   = (const float*)d_in[5];
    const float* Wo   = (const float*)d_in[6];
    float* out = (float*)d_out;

    float *qb, *kb, *vb;
    __half *ab, *xh, *wh;
    cudaGetSymbolAddress((void**)&qb, g_q);
    cudaGetSymbolAddress((void**)&kb, g_k);
    cudaGetSymbolAddress((void**)&vb, g_v);
    cudaGetSymbolAddress((void**)&ab, g_attn);
    cudaGetSymbolAddress((void**)&xh, g_xh);
    cudaGetSymbolAddress((void**)&wh, g_wh);

    cudaFuncSetAttribute(attn_kernel,
                         cudaFuncAttributeMaxDynamicSharedMemorySize,
                         AT_SMEM_BYTES);
    cudaFuncSetAttribute(gemm_f16_pipe,
                         cudaFuncAttributeMaxDynamicSharedMemorySize,
                         GSMEM_BYTES);

    const int BIG = 1 << 30;

    // one pass: X + all weights -> fp16
    cvt_all_kernel<<<(CVT_TOT4_ + 255) / 256, 256>>>(X, Wq, Wk, Wv, Wo);

    // Q projection: [8192 x 2048]
    gemm_f16_pipe<<<dim3(QDIM_ / 128, NTOK_ / 128), 256, GSMEM_BYTES>>>(
        xh, wh + WQ_OFF_, qb, qb, BIG, QDIM_, H_);

    // fused K+V projection: weights contiguous [1024 x 2048]; split at col 512
    gemm_f16_pipe<<<dim3(2 * KVDIM_ / 128, NTOK_ / 128), 256, GSMEM_BYTES>>>(
        xh, wh + WK_OFF_, kb, vb, KVDIM_, KVDIM_, H_);

    // RoPE on Q and K
    int rope_total = NTOK_ * (NH_ + NKV_) * (D_ / 2);
    rope_kernel<<<(rope_total + 255) / 256, 256>>>(cosp, sinp);

    // block-sparse attention (writes fp16 to g_attn)
    attn_kernel<<<dim3(KB_, NH_, B_), 256, AT_SMEM_BYTES>>>();

    // O projection
    gemm_f16_pipe<<<dim3(H_ / 128, NTOK_ / 128), 256, GSMEM_BYTES>>>(
        ab, wh + WO_OFF_, out, out, BIG, H_, QDIM_);
}

// round 14
// speedup vs baseline: 1.4055x; 1.4055x over previous
#include <cuda_runtime.h>
#include <cuda_fp16.h>
#include <cstdint>

// ---------------- problem constants ----------------
#define B_      2
#define S_      4096
#define H_      2048
#define NH_     16
#define NKV_    4
#define D_      128
#define BS_     64
#define KB_     (S_ / BS_)
#define NGLOB_  4
#define NLOCAL_ 8
#define NSEL_   (NGLOB_ + NLOCAL_)
#define STRIDE_ 16
#define NTOK_   (B_ * S_)       // 8192
#define QDIM_   (NH_ * D_)      // 2048
#define KVDIM_  (NKV_ * D_)     // 512
#define SCALE_  0.088388347648318447f
#define NEG_    (-1000000000.0f)

// ---------------- scratch ---------------------------------------------------
__device__ float  g_q[(size_t)NTOK_ * QDIM_];
__device__ float  g_k[(size_t)NTOK_ * KVDIM_];
__device__ float  g_v[(size_t)NTOK_ * KVDIM_];
__device__ __half g_attn[(size_t)NTOK_ * QDIM_];      // attention out (fp16)
__device__ __half g_xh[(size_t)NTOK_ * H_];           // X in fp16
// Q/K hi-lo split planes (post-RoPE)
__device__ __half g_qhi[(size_t)NTOK_ * QDIM_];
__device__ __half g_qlo[(size_t)NTOK_ * QDIM_];
__device__ __half g_khi[(size_t)NTOK_ * KVDIM_];
__device__ __half g_klo[(size_t)NTOK_ * KVDIM_];
// V transposed split planes: [(b*NKV+kvh)*D + d][s]
__device__ __half g_vthi[(size_t)B_ * NKV_ * D_ * S_];
__device__ __half g_vtlo[(size_t)B_ * NKV_ * D_ * S_];
// weights fp16: [Wq 4M][Wk 1M][Wv 1M][Wo 4M] halves
#define WQ_OFF_ 0
#define WK_OFF_ ((size_t)QDIM_ * H_)
#define WV_OFF_ (WK_OFF_ + (size_t)KVDIM_ * H_)
#define WO_OFF_ (WV_OFF_ + (size_t)KVDIM_ * H_)
#define WH_HALVES_ (WO_OFF_ + (size_t)QDIM_ * H_)
__device__ __half g_wh[WH_HALVES_];

// ---------------- helpers ---------------------------------------------------
__device__ __forceinline__ void mma_f16_k16(float* c, const uint32_t* a, const uint32_t* b) {
    asm volatile(
        "mma.sync.aligned.m16n8k16.row.col.f32.f16.f16.f32 "
        "{%0,%1,%2,%3}, {%4,%5,%6,%7}, {%8,%9}, {%0,%1,%2,%3};\n"
        : "+f"(c[0]), "+f"(c[1]), "+f"(c[2]), "+f"(c[3])
        : "r"(a[0]), "r"(a[1]), "r"(a[2]), "r"(a[3]), "r"(b[0]), "r"(b[1]));
}
__device__ __forceinline__ void cp_async16(uint32_t saddr, const void* gptr) {
    asm volatile("cp.async.cg.shared.global [%0], [%1], 16;\n"
                 :: "r"(saddr), "l"(gptr));
}
__device__ __forceinline__ void split_f16(float x, __half& hi, __half& lo) {
    hi = __float2half_rn(x);
    lo = __float2half_rn(x - __half2float(hi));
}

// ---------------- merged fp32 -> fp16 conversion ----------------------------
#define CVT_X4_   (NTOK_ * (H_ / 4))
#define CVT_WQ4_  (QDIM_ * (H_ / 4))
#define CVT_WK4_  (KVDIM_ * (H_ / 4))
#define CVT_TOT4_ (CVT_X4_ + CVT_WQ4_ + 2 * CVT_WK4_ + CVT_WQ4_)

__global__ void cvt_all_kernel(const float* __restrict__ X,
                               const float* __restrict__ Wq,
                               const float* __restrict__ Wk,
                               const float* __restrict__ Wv,
                               const float* __restrict__ Wo)
{
    int i = blockIdx.x * blockDim.x + threadIdx.x;
    if (i >= CVT_TOT4_) return;

    const float4* src;
    uint2* dst;
    if (i < CVT_X4_) {
        src = (const float4*)X + i;
        dst = (uint2*)g_xh + i;
    } else if (i < CVT_X4_ + CVT_WQ4_) {
        int j = i - CVT_X4_;
        src = (const float4*)Wq + j;
        dst = (uint2*)(g_wh + WQ_OFF_) + j;
    } else if (i < CVT_X4_ + CVT_WQ4_ + CVT_WK4_) {
        int j = i - CVT_X4_ - CVT_WQ4_;
        src = (const float4*)Wk + j;
        dst = (uint2*)(g_wh + WK_OFF_) + j;
    } else if (i < CVT_X4_ + CVT_WQ4_ + 2 * CVT_WK4_) {
        int j = i - CVT_X4_ - CVT_WQ4_ - CVT_WK4_;
        src = (const float4*)Wv + j;
        dst = (uint2*)(g_wh + WV_OFF_) + j;
    } else {
        int j = i - CVT_X4_ - CVT_WQ4_ - 2 * CVT_WK4_;
        src = (const float4*)Wo + j;
        dst = (uint2*)(g_wh + WO_OFF_) + j;
    }
    float4 v = *src;
    __half2 h0 = __floats2half2_rn(v.x, v.y);
    __half2 h1 = __floats2half2_rn(v.z, v.w);
    uint2 o;
    o.x = *(uint32_t*)&h0;
    o.y = *(uint32_t*)&h1;
    *dst = o;
}

// ---------------- pipelined fp16 GEMM (unchanged) ---------------------------
#define BKH_  32
#define LDHW_ 20
#define GSTG_ 4
#define ST_WORDS_ (2 * 128 * LDHW_)
#define GSMEM_BYTES (GSTG_ * ST_WORDS_ * 4)      // 81920

__global__ void __launch_bounds__(256, 2)
gemm_f16_pipe(const __half* __restrict__ A, const __half* __restrict__ B,
              float* __restrict__ C0, float* __restrict__ C1,
              int Nsplit, int ldc, int K)
{
    extern __shared__ uint32_t smg[];

    const size_t bm = (size_t)blockIdx.y * 128;
    const size_t bn = (size_t)blockIdx.x * 128;
    const int t = threadIdx.x;
    const int lane = t & 31, warp = t >> 5;
    const int g  = lane >> 2, tg = lane & 3;
    const int wm = (warp >> 2) * 64;
    const int wn = (warp & 3) * 32;

    float acc[4][4][4];
#pragma unroll
    for (int mi = 0; mi < 4; mi++)
#pragma unroll
        for (int ni = 0; ni < 4; ni++)
#pragma unroll
            for (int c = 0; c < 4; c++) acc[mi][ni][c] = 0.0f;

    auto load_stage = [&](int s, int i) {
        uint32_t* as = smg + s * ST_WORDS_;
        uint32_t* bs = as + 128 * LDHW_;
        const int k0 = i * BKH_;
#pragma unroll
        for (int j = 0; j < 2; j++) {
            int idx = t + j * 256;
            int row = idx >> 2, c4 = idx & 3;
            uint32_t sa = (uint32_t)__cvta_generic_to_shared(&as[row * LDHW_ + c4 * 4]);
            cp_async16(sa, A + (bm + row) * (size_t)K + k0 + c4 * 8);
            uint32_t sb = (uint32_t)__cvta_generic_to_shared(&bs[row * LDHW_ + c4 * 4]);
            cp_async16(sb, B + (bn + row) * (size_t)K + k0 + c4 * 8);
        }
        asm volatile("cp.async.commit_group;\n");
    };

    auto compute_stage = [&](int s) {
        const uint32_t* as = smg + s * ST_WORDS_;
        const uint32_t* bs = as + 128 * LDHW_;
#pragma unroll
        for (int kk = 0; kk < 2; kk++) {
            const int kb = kk * 8;
            uint32_t a[4][4];
#pragma unroll
            for (int mi = 0; mi < 4; mi++) {
                const int m0 = wm + mi * 16;
                a[mi][0] = as[(m0 + g) * LDHW_ + kb + tg];
                a[mi][1] = as[(m0 + g + 8) * LDHW_ + kb + tg];
                a[mi][2] = as[(m0 + g) * LDHW_ + kb + tg + 4];
                a[mi][3] = as[(m0 + g + 8) * LDHW_ + kb + tg + 4];
            }
            uint32_t bf[4][2];
#pragma unroll
            for (int ni = 0; ni < 4; ni++) {
                const int n0 = wn + ni * 8;
                bf[ni][0] = bs[(n0 + g) * LDHW_ + kb + tg];
                bf[ni][1] = bs[(n0 + g) * LDHW_ + kb + tg + 4];
            }
#pragma unroll
            for (int mi = 0; mi < 4; mi++)
#pragma unroll
                for (int ni = 0; ni < 4; ni++)
                    mma_f16_k16(acc[mi][ni], a[mi], bf[ni]);
        }
    };

    const int niter = K / BKH_;
    load_stage(0, 0);
    load_stage(1, 1);
    load_stage(2, 2);

    for (int i = 0; i < niter - 1; i++) {
        asm volatile("cp.async.wait_group 2;\n" ::: "memory");
        __syncthreads();
        if (i + 3 < niter) load_stage((i + 3) % GSTG_, i + 3);
        compute_stage(i % GSTG_);
    }
    asm volatile("cp.async.wait_group 0;\n" ::: "memory");
    __syncthreads();
    compute_stage((niter - 1) % GSTG_);

    float* C = C0;
    int cb = (int)bn;
    if (cb >= Nsplit) { C = C1; cb -= Nsplit; }

#pragma unroll
    for (int mi = 0; mi < 4; mi++) {
        const size_t row = bm + wm + mi * 16 + g;
#pragma unroll
        for (int ni = 0; ni < 4; ni++) {
            const int col = cb + wn + ni * 8 + 2 * tg;
            float* cp0 = C + row * ldc + col;
            float* cp1 = cp0 + (size_t)8 * ldc;
            *(float2*)cp0 = make_float2(acc[mi][ni][0], acc[mi][ni][1]);
            *(float2*)cp1 = make_float2(acc[mi][ni][2], acc[mi][ni][3]);
        }
    }
}

// ---------------- RoPE: rotate + fp16 hi/lo split to planes -----------------
__global__ void rope_kernel(const float* __restrict__ cosp,
                            const float* __restrict__ sinp)
{
    int idx = blockIdx.x * blockDim.x + threadIdx.x;
    const int total = NTOK_ * (NH_ + NKV_) * (D_ / 2);
    if (idx >= total) return;

    int d    = idx % (D_ / 2);
    int rest = idx / (D_ / 2);
    int h    = rest % (NH_ + NKV_);
    int tok  = rest / (NH_ + NKV_);

    float c1 = cosp[(size_t)tok * D_ + d];
    float s1 = sinp[(size_t)tok * D_ + d];
    float c2 = cosp[(size_t)tok * D_ + d + D_ / 2];
    float s2 = sinp[(size_t)tok * D_ + d + D_ / 2];

    const float* buf;
    __half *hip, *lop;
    size_t off;
    if (h < NH_) {
        off = (size_t)tok * QDIM_ + h * D_;
        buf = g_q + off; hip = g_qhi + off; lop = g_qlo + off;
    } else {
        off = (size_t)tok * KVDIM_ + (h - NH_) * D_;
        buf = g_k + off; hip = g_khi + off; lop = g_klo + off;
    }

    float x1 = buf[d];
    float x2 = buf[d + D_ / 2];
    float o1 = x1 * c1 - x2 * s1;
    float o2 = x2 * c2 + x1 * s2;

    __half h1v, l1v, h2v, l2v;
    split_f16(o1, h1v, l1v);
    split_f16(o2, h2v, l2v);
    hip[d] = h1v;            lop[d] = l1v;
    hip[d + D_ / 2] = h2v;   lop[d + D_ / 2] = l2v;
}

// ---------------- V transpose + split:  vt[(bkv*D+d)*S + s] -----------------
__global__ void cvt_v_kernel()
{
    int idx = blockIdx.x * blockDim.x + threadIdx.x;
    const int total = B_ * NKV_ * D_ * S_;
    if (idx >= total) return;
    int s    = idx % S_;
    int rest = idx / S_;
    int d    = rest % D_;
    int bkv  = rest / D_;
    int b    = bkv / NKV_;
    int kvh  = bkv % NKV_;
    float x = g_v[((size_t)(b * S_ + s)) * KVDIM_ + kvh * D_ + d];
    __half hi, lo;
    split_f16(x, hi, lo);
    g_vthi[idx] = hi;
    g_vtlo[idx] = lo;
}

// ---------------- block-sparse attention (fp16 split planes) ----------------
// smem halves: QHI[64][136] QLO KHI KLO VTHI[128][72] VTLO ; P aliases K.
#define QLDW_  68      // Q/K row stride in words (136 halves)
#define VLDW_  36      // VT/P row stride in words (72 halves)
#define QHI_O_ 0
#define QLO_O_ 8704
#define KHI_O_ 17408
#define KLO_O_ 26112
#define VTHI_O_ 34816
#define VTLO_O_ 44032
#define SMH_HALVES_ 53248
#define AT_STAT_FLOATS (128 + 128 + 3 * 64)
#define AT_SMEM_BYTES (SMH_HALVES_ * 2 + AT_STAT_FLOATS * 4)   // 108288

__global__ void __launch_bounds__(256, 2)
attn_kernel()
{
    extern __shared__ __half smh[];
    float* stat = (float*)(smh + SMH_HALVES_);
    float* wmax = stat;                // [2][64]
    float* wsum = wmax + 128;          // [2][64]
    float* rowm = wsum + 128;
    float* rowl = rowm + 64;
    float* rowf = rowl + 64;
    __shared__ int sel_s[NSEL_];
    __shared__ int keep_s[NSEL_];
    __shared__ int klist[NSEL_];
    __shared__ int kcnt;

    const uint32_t* qhiw = (const uint32_t*)(smh + QHI_O_);
    const uint32_t* qlow = (const uint32_t*)(smh + QLO_O_);
    const uint32_t* khiw = (const uint32_t*)(smh + KHI_O_);
    const uint32_t* klow = (const uint32_t*)(smh + KLO_O_);
    const uint32_t* vhiw = (const uint32_t*)(smh + VTHI_O_);
    const uint32_t* vlow = (const uint32_t*)(smh + VTLO_O_);
    __half* phi = smh + KHI_O_;        // P hi aliases K hi
    __half* plo = smh + KLO_O_;        // P lo aliases K lo
    const uint32_t* phiw = (const uint32_t*)phi;
    const uint32_t* plow = (const uint32_t*)plo;

    const int qid = blockIdx.x;
    const int h   = blockIdx.y;
    const int b   = blockIdx.z;
    const int t   = threadIdx.x;
    const int kvh = h / (NH_ / NKV_);
    const int bkv = b * NKV_ + kvh;

    const int warp = t >> 5, lane = t & 31;
    const int g  = lane >> 2;
    const int tg = lane & 3;
    const int wm  = (warp >> 1) * 16;
    const int nh  = warp & 1;
    const int wn  = nh * 32;
    const int wn2 = nh * 64;
    const int row0 = wm + g;
    const int row1 = wm + g + 8;

    // block selection + dedup + compaction
    if (t < NSEL_) {
        int s;
        if (t < NGLOB_) { s = t * STRIDE_; if (s > KB_ - 1) s = KB_ - 1; }
        else            { int j = t - NGLOB_; s = qid - (NLOCAL_ - 1) + j;
                          s = s < 0 ? 0 : (s > KB_ - 1 ? KB_ - 1 : s); }
        bool valid = (s <= qid);
        bool dup = false;
        for (int jj = 0; jj < t; jj++) {
            int sj;
            if (jj < NGLOB_) { sj = jj * STRIDE_; if (sj > KB_ - 1) sj = KB_ - 1; }
            else             { int j2 = jj - NGLOB_; sj = qid - (NLOCAL_ - 1) + j2;
                               sj = sj < 0 ? 0 : (sj > KB_ - 1 ? KB_ - 1 : sj); }
            if (sj == s) dup = true;
        }
        sel_s[t]  = s;
        keep_s[t] = (valid && !dup) ? 1 : 0;
    }
    if (t < 64) { rowm[t] = -1e30f; rowl[t] = 0.0f; }
    __syncthreads();
    if (t == 0) {
        int c = 0;
        for (int j = 0; j < NSEL_; j++)
            if (keep_s[j]) klist[c++] = sel_s[j];
        kcnt = c;
    }
    __syncthreads();
    const int cnt = kcnt;

    // loaders: each tile = 2048 x 16B chunks (hi+lo planes), 8 per thread
    auto load_k = [&](int kblk) {
        const __half* shi = g_khi + ((size_t)(b * S_ + kblk * BS_)) * KVDIM_ + kvh * D_;
        const __half* slo = g_klo + ((size_t)(b * S_ + kblk * BS_)) * KVDIM_ + kvh * D_;
#pragma unroll
        for (int j = 0; j < 8; j++) {
            int idx = t + j * 256;
            int pl = idx >> 10, r = (idx >> 4) & 63, c = idx & 15;
            const __half* src = (pl ? slo : shi) + (size_t)r * KVDIM_ + c * 8;
            __half* dstb = smh + (pl ? KLO_O_ : KHI_O_) + r * 136 + c * 8;
            cp_async16((uint32_t)__cvta_generic_to_shared(dstb), src);
        }
        asm volatile("cp.async.commit_group;\n");
    };
    auto load_v = [&](int kblk) {
        const __half* shi = g_vthi + ((size_t)bkv * D_) * S_ + kblk * BS_;
        const __half* slo = g_vtlo + ((size_t)bkv * D_) * S_ + kblk * BS_;
#pragma unroll
        for (int j = 0; j < 8; j++) {
            int idx = t + j * 256;
            int pl = idx >> 10, r = (idx >> 3) & 127, c = idx & 7;
            const __half* src = (pl ? slo : shi) + (size_t)r * S_ + c * 8;
            __half* dstb = smh + (pl ? VTLO_O_ : VTHI_O_) + r * 72 + c * 8;
            cp_async16((uint32_t)__cvta_generic_to_shared(dstb), src);
        }
        asm volatile("cp.async.commit_group;\n");
    };

    // prologue: K[0] then Q planes
    load_k(klist[0]);
    {
        const __half* shi = g_qhi + ((size_t)(b * S_ + qid * BS_)) * QDIM_ + h * D_;
        const __half* slo = g_qlo + ((size_t)(b * S_ + qid * BS_)) * QDIM_ + h * D_;
#pragma unroll
        for (int j = 0; j < 8; j++) {
            int idx = t + j * 256;
            int pl = idx >> 10, r = (idx >> 4) & 63, c = idx & 15;
            const __half* src = (pl ? slo : shi) + (size_t)r * QDIM_ + c * 8;
            __half* dstb = smh + (pl ? QLO_O_ : QHI_O_) + r * 136 + c * 8;
            cp_async16((uint32_t)__cvta_generic_to_shared(dstb), src);
        }
        asm volatile("cp.async.commit_group;\n");
    }

    float o[8][4];
#pragma unroll
    for (int ni = 0; ni < 8; ni++)
#pragma unroll
        for (int c = 0; c < 4; c++) o[ni][c] = 0.0f;

    for (int bi = 0; bi < cnt; bi++) {
        const int kblk = klist[bi];
        const bool diag = (kblk == qid);

        asm volatile("cp.async.wait_group 0;\n" ::: "memory");
        __syncthreads();

        // V[bi] load proceeds under S-mma + softmax
        load_v(kblk);

        // ---- S = Q @ K^T : 3-term fp16 split, m16n8k16
        float sacc[4][4];
#pragma unroll
        for (int ni = 0; ni < 4; ni++)
#pragma unroll
            for (int c = 0; c < 4; c++) sacc[ni][c] = 0.0f;

#pragma unroll
        for (int ks = 0; ks < 8; ks++) {
            const int kb = ks * 8;
            uint32_t ah[4], al[4];
            ah[0] = qhiw[row0 * QLDW_ + kb + tg];
            ah[1] = qhiw[row1 * QLDW_ + kb + tg];
            ah[2] = qhiw[row0 * QLDW_ + kb + tg + 4];
            ah[3] = qhiw[row1 * QLDW_ + kb + tg + 4];
            al[0] = qlow[row0 * QLDW_ + kb + tg];
            al[1] = qlow[row1 * QLDW_ + kb + tg];
            al[2] = qlow[row0 * QLDW_ + kb + tg + 4];
            al[3] = qlow[row1 * QLDW_ + kb + tg + 4];
#pragma unroll
            for (int ni = 0; ni < 4; ni++) {
                const int n = wn + ni * 8 + g;
                uint32_t bh[2], bl[2];
                bh[0] = khiw[n * QLDW_ + kb + tg];
                bh[1] = khiw[n * QLDW_ + kb + tg + 4];
                bl[0] = klow[n * QLDW_ + kb + tg];
                bl[1] = klow[n * QLDW_ + kb + tg + 4];
                mma_f16_k16(sacc[ni], ah, bh);
                mma_f16_k16(sacc[ni], ah, bl);
                mma_f16_k16(sacc[ni], al, bh);
            }
        }

        // ---- scale + mask + partial max
        float pm0 = -1e30f, pm1 = -1e30f;
#pragma unroll
        for (int ni = 0; ni < 4; ni++) {
            const int colb = wn + ni * 8 + 2 * tg;
#pragma unroll
            for (int c = 0; c < 4; c++) {
                const int col = colb + (c & 1);
                const int row = (c < 2) ? row0 : row1;
                float v = sacc[ni][c] * SCALE_;
                if (diag && col > row) v += NEG_;
                sacc[ni][c] = v;
                if (c < 2) pm0 = fmaxf(pm0, v);
                else       pm1 = fmaxf(pm1, v);
            }
        }
        pm0 = fmaxf(pm0, __shfl_xor_sync(0xffffffff, pm0, 1));
        pm0 = fmaxf(pm0, __shfl_xor_sync(0xffffffff, pm0, 2));
        pm1 = fmaxf(pm1, __shfl_xor_sync(0xffffffff, pm1, 1));
        pm1 = fmaxf(pm1, __shfl_xor_sync(0xffffffff, pm1, 2));
        if (tg == 0) {
            wmax[nh * 64 + row0] = pm0;
            wmax[nh * 64 + row1] = pm1;
        }
        __syncthreads();   // K planes fully consumed; P overwrite safe after

        float mx0 = fmaxf(fmaxf(wmax[row0], wmax[64 + row0]), rowm[row0]);
        float mx1 = fmaxf(fmaxf(wmax[row1], wmax[64 + row1]), rowm[row1]);
        float ps0 = 0.0f, ps1 = 0.0f;
#pragma unroll
        for (int ni = 0; ni < 4; ni++) {
#pragma unroll
            for (int c = 0; c < 4; c++) {
                float p = __expf(sacc[ni][c] - ((c < 2) ? mx0 : mx1));
                sacc[ni][c] = p;
                if (c < 2) ps0 += p; else ps1 += p;
            }
        }
        ps0 += __shfl_xor_sync(0xffffffff, ps0, 1);
        ps0 += __shfl_xor_sync(0xffffffff, ps0, 2);
        ps1 += __shfl_xor_sync(0xffffffff, ps1, 1);
        ps1 += __shfl_xor_sync(0xffffffff, ps1, 2);
        if (tg == 0) {
            wsum[nh * 64 + row0] = ps0;
            wsum[nh * 64 + row1] = ps1;
        }
        float mxt = 0.0f, ft = 0.0f;
        if (t < 64) {
            mxt = fmaxf(fmaxf(wmax[t], wmax[64 + t]), rowm[t]);
            ft  = __expf(rowm[t] - mxt);
            rowf[t] = ft;
        }
        __syncthreads();

        if (t < 64) {
            rowl[t] = rowl[t] * ft + wsum[t] + wsum[64 + t];
            rowm[t] = mxt;
        }

        // rescale O; split P into hi/lo planes (aliasing K)
        {
            float f0 = rowf[row0], f1 = rowf[row1];
#pragma unroll
            for (int ni = 0; ni < 8; ni++) {
                o[ni][0] *= f0; o[ni][1] *= f0;
                o[ni][2] *= f1; o[ni][3] *= f1;
            }
        }
#pragma unroll
        for (int ni = 0; ni < 4; ni++) {
            const int colb = wn + ni * 8 + 2 * tg;
            __half h0, l0, h1, l1;
            split_f16(sacc[ni][0], h0, l0);
            split_f16(sacc[ni][1], h1, l1);
            *(__half2*)(phi + row0 * 72 + colb) = __halves2half2(h0, h1);
            *(__half2*)(plo + row0 * 72 + colb) = __halves2half2(l0, l1);
            split_f16(sacc[ni][2], h0, l0);
            split_f16(sacc[ni][3], h1, l1);
            *(__half2*)(phi + row1 * 72 + colb) = __halves2half2(h0, h1);
            *(__half2*)(plo + row1 * 72 + colb) = __halves2half2(l0, l1);
        }

        // V ready + P visible
        asm volatile("cp.async.wait_group 0;\n" ::: "memory");
        __syncthreads();

        // ---- O += P @ V : 3-term fp16 split, m16n8k16 (B = V transposed)
#pragma unroll
        for (int ks = 0; ks < 4; ks++) {
            const int kb = ks * 8;
            uint32_t ah[4], al[4];
            ah[0] = phiw[row0 * VLDW_ + kb + tg];
            ah[1] = phiw[row1 * VLDW_ + kb + tg];
            ah[2] = phiw[row0 * VLDW_ + kb + tg + 4];
            ah[3] = phiw[row1 * VLDW_ + kb + tg + 4];
            al[0] = plow[row0 * VLDW_ + kb + tg];
            al[1] = plow[row1 * VLDW_ + kb + tg];
            al[2] = plow[row0 * VLDW_ + kb + tg + 4];
            al[3] = plow[row1 * VLDW_ + kb + tg + 4];
#pragma unroll
            for (int ni = 0; ni < 8; ni++) {
                const int n = wn2 + ni * 8 + g;
                uint32_t bh[2], bl[2];
                bh[0] = vhiw[n * VLDW_ + kb + tg];
                bh[1] = vhiw[n * VLDW_ + kb + tg + 4];
                bl[0] = vlow[n * VLDW_ + kb + tg];
                bl[1] = vlow[n * VLDW_ + kb + tg + 4];
                mma_f16_k16(o[ni], ah, bh);
                mma_f16_k16(o[ni], ah, bl);
                mma_f16_k16(o[ni], al, bh);
            }
        }
        __syncthreads();   // P/V reads complete

        if (bi + 1 < cnt) load_k(klist[bi + 1]);
    }

    // finalize: divide by denom, write fp16 (feeds O projection)
    const float invl0 = 1.0f / rowl[row0];
    const float invl1 = 1.0f / rowl[row1];
    __half* ob0 = g_attn + ((size_t)(b * S_ + qid * BS_ + row0)) * QDIM_ + h * D_;
    __half* ob1 = g_attn + ((size_t)(b * S_ + qid * BS_ + row1)) * QDIM_ + h * D_;
#pragma unroll
    for (int ni = 0; ni < 8; ni++) {
        const int col = wn2 + ni * 8 + 2 * tg;
        __half2 h0 = __floats2half2_rn(o[ni][0] * invl0, o[ni][1] * invl0);
        __half2 h1 = __floats2half2_rn(o[ni][2] * invl1, o[ni][3] * invl1);
        *(__half2*)(ob0 + col) = h0;
        *(__half2*)(ob1 + col) = h1;
    }
}

// ---------------- host launcher ---------------------------------------------
extern "C" void kernel_launch(void* const* d_in, const int* in_sizes, int n_in,
                              void* d_out, int out_size)
{
    const float* X    = (const float*)d_in[0];
    const float* cosp = (const float*)d_in[1];
    const float* sinp = (const float*)d_in[2];
    const float* Wq   = (const float*)d_in[3];
    const float* Wk   = (const float*)d_in[4];
    const float* Wv   = (const float*)d_in[5];
    const float* Wo   = (const float*)d_in[6];
    float* out = (float*)d_out;

    float *qb, *kb, *vb;
    __half *ab, *xh, *wh;
    cudaGetSymbolAddress((void**)&qb, g_q);
    cudaGetSymbolAddress((void**)&kb, g_k);
    cudaGetSymbolAddress((void**)&vb, g_v);
    cudaGetSymbolAddress((void**)&ab, g_attn);
    cudaGetSymbolAddress((void**)&xh, g_xh);
    cudaGetSymbolAddress((void**)&wh, g_wh);

    cudaFuncSetAttribute(attn_kernel,
                         cudaFuncAttributeMaxDynamicSharedMemorySize,
                         AT_SMEM_BYTES);
    cudaFuncSetAttribute(gemm_f16_pipe,
                         cudaFuncAttributeMaxDynamicSharedMemorySize,
                         GSMEM_BYTES);

    const int BIG = 1 << 30;

    // one pass: X + all weights -> fp16
    cvt_all_kernel<<<(CVT_TOT4_ + 255) / 256, 256>>>(X, Wq, Wk, Wv, Wo);

    // Q projection: [8192 x 2048]
    gemm_f16_pipe<<<dim3(QDIM_ / 128, NTOK_ / 128), 256, GSMEM_BYTES>>>(
        xh, wh + WQ_OFF_, qb, qb, BIG, QDIM_, H_);

    // fused K+V projection: weights contiguous [1024 x 2048]; split at col 512
    gemm_f16_pipe<<<dim3(2 * KVDIM_ / 128, NTOK_ / 128), 256, GSMEM_BYTES>>>(
        xh, wh + WK_OFF_, kb, vb, KVDIM_, KVDIM_, H_);

    // RoPE: rotate + write Q/K fp16 split planes
    int rope_total = NTOK_ * (NH_ + NKV_) * (D_ / 2);
    rope_kernel<<<(rope_total + 255) / 256, 256>>>(cosp, sinp);

    // V transpose + split planes
    int vtot = B_ * NKV_ * D_ * S_;
    cvt_v_kernel<<<(vtot + 255) / 256, 256>>>();

    // block-sparse attention (fp16 split planes, writes fp16 to g_attn)
    attn_kernel<<<dim3(KB_, NH_, B_), 256, AT_SMEM_BYTES>>>();

    // O projection
    gemm_f16_pipe<<<dim3(H_ / 128, NTOK_ / 128), 256, GSMEM_BYTES>>>(
        ab, wh + WO_OFF_, out, out, BIG, H_, QDIM_);
}

// round 15
// speedup vs baseline: 1.4777x; 1.0514x over previous
#include <cuda_runtime.h>
#include <cuda_fp16.h>
#include <cstdint>

// ---------------- problem constants ----------------
#define B_      2
#define S_      4096
#define H_      2048
#define NH_     16
#define NKV_    4
#define D_      128
#define BS_     64
#define KB_     (S_ / BS_)
#define NGLOB_  4
#define NLOCAL_ 8
#define NSEL_   (NGLOB_ + NLOCAL_)
#define STRIDE_ 16
#define NTOK_   (B_ * S_)       // 8192
#define QDIM_   (NH_ * D_)      // 2048
#define KVDIM_  (NKV_ * D_)     // 512
#define SCALE_  0.088388347648318447f
#define NEG_    (-1000000000.0f)

// ---------------- scratch ---------------------------------------------------
__device__ float  g_q[(size_t)NTOK_ * QDIM_];
__device__ float  g_k[(size_t)NTOK_ * KVDIM_];
__device__ float  g_v[(size_t)NTOK_ * KVDIM_];
__device__ __half g_attn[(size_t)NTOK_ * QDIM_];      // attention out (fp16)
__device__ __half g_xh[(size_t)NTOK_ * H_];           // X in fp16
// Q/K hi-lo split planes (post-RoPE)
__device__ __half g_qhi[(size_t)NTOK_ * QDIM_];
__device__ __half g_qlo[(size_t)NTOK_ * QDIM_];
__device__ __half g_khi[(size_t)NTOK_ * KVDIM_];
__device__ __half g_klo[(size_t)NTOK_ * KVDIM_];
// V transposed split planes: [(b*NKV+kvh)*D + d][s]
__device__ __half g_vthi[(size_t)B_ * NKV_ * D_ * S_];
__device__ __half g_vtlo[(size_t)B_ * NKV_ * D_ * S_];
// weights fp16: [Wq 4M][Wk 1M][Wv 1M][Wo 4M] halves
#define WQ_OFF_ 0
#define WK_OFF_ ((size_t)QDIM_ * H_)
#define WV_OFF_ (WK_OFF_ + (size_t)KVDIM_ * H_)
#define WO_OFF_ (WV_OFF_ + (size_t)KVDIM_ * H_)
#define WH_HALVES_ (WO_OFF_ + (size_t)QDIM_ * H_)
__device__ __half g_wh[WH_HALVES_];

// ---------------- helpers ---------------------------------------------------
__device__ __forceinline__ void mma_f16_k16(float* c, const uint32_t* a, const uint32_t* b) {
    asm volatile(
        "mma.sync.aligned.m16n8k16.row.col.f32.f16.f16.f32 "
        "{%0,%1,%2,%3}, {%4,%5,%6,%7}, {%8,%9}, {%0,%1,%2,%3};\n"
        : "+f"(c[0]), "+f"(c[1]), "+f"(c[2]), "+f"(c[3])
        : "r"(a[0]), "r"(a[1]), "r"(a[2]), "r"(a[3]), "r"(b[0]), "r"(b[1]));
}
__device__ __forceinline__ void cp_async16(uint32_t saddr, const void* gptr) {
    asm volatile("cp.async.cg.shared.global [%0], [%1], 16;\n"
                 :: "r"(saddr), "l"(gptr));
}
__device__ __forceinline__ void split_f16(float x, __half& hi, __half& lo) {
    hi = __float2half_rn(x);
    lo = __float2half_rn(x - __half2float(hi));
}
__device__ __forceinline__ void ldsm_x4(uint32_t& r0, uint32_t& r1,
                                        uint32_t& r2, uint32_t& r3, uint32_t addr) {
    asm volatile("ldmatrix.sync.aligned.m8n8.x4.shared.b16 {%0,%1,%2,%3}, [%4];"
                 : "=r"(r0), "=r"(r1), "=r"(r2), "=r"(r3) : "r"(addr));
}

// ---------------- merged fp32 -> fp16 conversion ----------------------------
#define CVT_X4_   (NTOK_ * (H_ / 4))
#define CVT_WQ4_  (QDIM_ * (H_ / 4))
#define CVT_WK4_  (KVDIM_ * (H_ / 4))
#define CVT_TOT4_ (CVT_X4_ + CVT_WQ4_ + 2 * CVT_WK4_ + CVT_WQ4_)

__global__ void cvt_all_kernel(const float* __restrict__ X,
                               const float* __restrict__ Wq,
                               const float* __restrict__ Wk,
                               const float* __restrict__ Wv,
                               const float* __restrict__ Wo)
{
    int i = blockIdx.x * blockDim.x + threadIdx.x;
    if (i >= CVT_TOT4_) return;

    const float4* src;
    uint2* dst;
    if (i < CVT_X4_) {
        src = (const float4*)X + i;
        dst = (uint2*)g_xh + i;
    } else if (i < CVT_X4_ + CVT_WQ4_) {
        int j = i - CVT_X4_;
        src = (const float4*)Wq + j;
        dst = (uint2*)(g_wh + WQ_OFF_) + j;
    } else if (i < CVT_X4_ + CVT_WQ4_ + CVT_WK4_) {
        int j = i - CVT_X4_ - CVT_WQ4_;
        src = (const float4*)Wk + j;
        dst = (uint2*)(g_wh + WK_OFF_) + j;
    } else if (i < CVT_X4_ + CVT_WQ4_ + 2 * CVT_WK4_) {
        int j = i - CVT_X4_ - CVT_WQ4_ - CVT_WK4_;
        src = (const float4*)Wv + j;
        dst = (uint2*)(g_wh + WV_OFF_) + j;
    } else {
        int j = i - CVT_X4_ - CVT_WQ4_ - 2 * CVT_WK4_;
        src = (const float4*)Wo + j;
        dst = (uint2*)(g_wh + WO_OFF_) + j;
    }
    float4 v = *src;
    __half2 h0 = __floats2half2_rn(v.x, v.y);
    __half2 h1 = __floats2half2_rn(v.z, v.w);
    uint2 o;
    o.x = *(uint32_t*)&h0;
    o.y = *(uint32_t*)&h1;
    *dst = o;
}

// ---------------- pipelined fp16 GEMM (ldmatrix + 5 stages) -----------------
#define BKH_  32
#define LDHW_ 20
#define GSTG_ 5
#define ST_WORDS_ (2 * 128 * LDHW_)
#define GSMEM_BYTES (GSTG_ * ST_WORDS_ * 4)      // 102400

__global__ void __launch_bounds__(256, 2)
gemm_f16_pipe(const __half* __restrict__ A, const __half* __restrict__ B,
              float* __restrict__ C0, float* __restrict__ C1,
              int Nsplit, int ldc, int K)
{
    extern __shared__ uint32_t smg[];

    const size_t bm = (size_t)blockIdx.y * 128;
    const size_t bn = (size_t)blockIdx.x * 128;
    const int t = threadIdx.x;
    const int lane = t & 31, warp = t >> 5;
    const int wm = (warp >> 2) * 64;
    const int wn = (warp & 3) * 32;
    const int g  = lane >> 2, tg = lane & 3;

    // ldmatrix per-lane address components (in words)
    const int arow = lane & 15;
    const int ak4  = (lane >> 4) << 2;
    const int brow = (lane & 7) + ((lane >> 4) << 3);
    const int bk4  = ((lane >> 3) & 1) << 2;

    const uint32_t smg_u32 = (uint32_t)__cvta_generic_to_shared(smg);

    float acc[4][4][4];
#pragma unroll
    for (int mi = 0; mi < 4; mi++)
#pragma unroll
        for (int ni = 0; ni < 4; ni++)
#pragma unroll
            for (int c = 0; c < 4; c++) acc[mi][ni][c] = 0.0f;

    auto load_stage = [&](int s, int i) {
        uint32_t* as = smg + s * ST_WORDS_;
        uint32_t* bs = as + 128 * LDHW_;
        const int k0 = i * BKH_;
#pragma unroll
        for (int j = 0; j < 2; j++) {
            int idx = t + j * 256;
            int row = idx >> 2, c4 = idx & 3;
            uint32_t sa = (uint32_t)__cvta_generic_to_shared(&as[row * LDHW_ + c4 * 4]);
            cp_async16(sa, A + (bm + row) * (size_t)K + k0 + c4 * 8);
            uint32_t sb = (uint32_t)__cvta_generic_to_shared(&bs[row * LDHW_ + c4 * 4]);
            cp_async16(sb, B + (bn + row) * (size_t)K + k0 + c4 * 8);
        }
        asm volatile("cp.async.commit_group;\n");
    };

    auto compute_stage = [&](int s) {
        const uint32_t a_st = smg_u32 + (s * ST_WORDS_) * 4;
        const uint32_t b_st = a_st + (128 * LDHW_) * 4;
#pragma unroll
        for (int kk = 0; kk < 2; kk++) {
            const int kb = kk * 8;
            uint32_t a[4][4];
#pragma unroll
            for (int mi = 0; mi < 4; mi++) {
                uint32_t addr = a_st + ((wm + mi * 16 + arow) * LDHW_ + kb + ak4) * 4;
                ldsm_x4(a[mi][0], a[mi][1], a[mi][2], a[mi][3], addr);
            }
            uint32_t bf[4][2];
#pragma unroll
            for (int np = 0; np < 2; np++) {
                uint32_t addr = b_st + ((wn + np * 16 + brow) * LDHW_ + kb + bk4) * 4;
                ldsm_x4(bf[2 * np][0], bf[2 * np][1],
                        bf[2 * np + 1][0], bf[2 * np + 1][1], addr);
            }
#pragma unroll
            for (int mi = 0; mi < 4; mi++)
#pragma unroll
                for (int ni = 0; ni < 4; ni++)
                    mma_f16_k16(acc[mi][ni], a[mi], bf[ni]);
        }
    };

    const int niter = K / BKH_;
    load_stage(0, 0);
    load_stage(1, 1);
    load_stage(2, 2);
    load_stage(3, 3);

    for (int i = 0; i < niter - 1; i++) {
        asm volatile("cp.async.wait_group 3;\n" ::: "memory");
        __syncthreads();
        if (i + 4 < niter) load_stage((i + 4) % GSTG_, i + 4);
        compute_stage(i % GSTG_);
    }
    asm volatile("cp.async.wait_group 0;\n" ::: "memory");
    __syncthreads();
    compute_stage((niter - 1) % GSTG_);

    float* C = C0;
    int cb = (int)bn;
    if (cb >= Nsplit) { C = C1; cb -= Nsplit; }

#pragma unroll
    for (int mi = 0; mi < 4; mi++) {
        const size_t row = bm + wm + mi * 16 + g;
#pragma unroll
        for (int ni = 0; ni < 4; ni++) {
            const int col = cb + wn + ni * 8 + 2 * tg;
            float* cp0 = C + row * ldc + col;
            float* cp1 = cp0 + (size_t)8 * ldc;
            *(float2*)cp0 = make_float2(acc[mi][ni][0], acc[mi][ni][1]);
            *(float2*)cp1 = make_float2(acc[mi][ni][2], acc[mi][ni][3]);
        }
    }
}

// ---------------- RoPE: rotate + fp16 hi/lo split to planes -----------------
__global__ void rope_kernel(const float* __restrict__ cosp,
                            const float* __restrict__ sinp)
{
    int idx = blockIdx.x * blockDim.x + threadIdx.x;
    const int total = NTOK_ * (NH_ + NKV_) * (D_ / 2);
    if (idx >= total) return;

    int d    = idx % (D_ / 2);
    int rest = idx / (D_ / 2);
    int h    = rest % (NH_ + NKV_);
    int tok  = rest / (NH_ + NKV_);

    float c1 = cosp[(size_t)tok * D_ + d];
    float s1 = sinp[(size_t)tok * D_ + d];
    float c2 = cosp[(size_t)tok * D_ + d + D_ / 2];
    float s2 = sinp[(size_t)tok * D_ + d + D_ / 2];

    const float* buf;
    __half *hip, *lop;
    size_t off;
    if (h < NH_) {
        off = (size_t)tok * QDIM_ + h * D_;
        buf = g_q + off; hip = g_qhi + off; lop = g_qlo + off;
    } else {
        off = (size_t)tok * KVDIM_ + (h - NH_) * D_;
        buf = g_k + off; hip = g_khi + off; lop = g_klo + off;
    }

    float x1 = buf[d];
    float x2 = buf[d + D_ / 2];
    float o1 = x1 * c1 - x2 * s1;
    float o2 = x2 * c2 + x1 * s2;

    __half h1v, l1v, h2v, l2v;
    split_f16(o1, h1v, l1v);
    split_f16(o2, h2v, l2v);
    hip[d] = h1v;            lop[d] = l1v;
    hip[d + D_ / 2] = h2v;   lop[d + D_ / 2] = l2v;
}

// ---------------- V transpose + split:  vt[(bkv*D+d)*S + s] -----------------
__global__ void cvt_v_kernel()
{
    int idx = blockIdx.x * blockDim.x + threadIdx.x;
    const int total = B_ * NKV_ * D_ * S_;
    if (idx >= total) return;
    int s    = idx % S_;
    int rest = idx / S_;
    int d    = rest % D_;
    int bkv  = rest / D_;
    int b    = bkv / NKV_;
    int kvh  = bkv % NKV_;
    float x = g_v[((size_t)(b * S_ + s)) * KVDIM_ + kvh * D_ + d];
    __half hi, lo;
    split_f16(x, hi, lo);
    g_vthi[idx] = hi;
    g_vtlo[idx] = lo;
}

// ---------------- block-sparse attention (fp16 split planes) ----------------
#define QLDW_  68
#define VLDW_  36
#define QHI_O_ 0
#define QLO_O_ 8704
#define KHI_O_ 17408
#define KLO_O_ 26112
#define VTHI_O_ 34816
#define VTLO_O_ 44032
#define SMH_HALVES_ 53248
#define AT_STAT_FLOATS (128 + 128 + 3 * 64)
#define AT_SMEM_BYTES (SMH_HALVES_ * 2 + AT_STAT_FLOATS * 4)   // 108288

__global__ void __launch_bounds__(256, 2)
attn_kernel()
{
    extern __shared__ __half smh[];
    float* stat = (float*)(smh + SMH_HALVES_);
    float* wmax = stat;
    float* wsum = wmax + 128;
    float* rowm = wsum + 128;
    float* rowl = rowm + 64;
    float* rowf = rowl + 64;
    __shared__ int sel_s[NSEL_];
    __shared__ int keep_s[NSEL_];
    __shared__ int klist[NSEL_];
    __shared__ int kcnt;

    const uint32_t* qhiw = (const uint32_t*)(smh + QHI_O_);
    const uint32_t* qlow = (const uint32_t*)(smh + QLO_O_);
    const uint32_t* khiw = (const uint32_t*)(smh + KHI_O_);
    const uint32_t* klow = (const uint32_t*)(smh + KLO_O_);
    const uint32_t* vhiw = (const uint32_t*)(smh + VTHI_O_);
    const uint32_t* vlow = (const uint32_t*)(smh + VTLO_O_);
    __half* phi = smh + KHI_O_;
    __half* plo = smh + KLO_O_;
    const uint32_t* phiw = (const uint32_t*)phi;
    const uint32_t* plow = (const uint32_t*)plo;

    const int qid = blockIdx.x;
    const int h   = blockIdx.y;
    const int b   = blockIdx.z;
    const int t   = threadIdx.x;
    const int kvh = h / (NH_ / NKV_);
    const int bkv = b * NKV_ + kvh;

    const int warp = t >> 5, lane = t & 31;
    const int g  = lane >> 2;
    const int tg = lane & 3;
    const int wm  = (warp >> 1) * 16;
    const int nh  = warp & 1;
    const int wn  = nh * 32;
    const int wn2 = nh * 64;
    const int row0 = wm + g;
    const int row1 = wm + g + 8;

    if (t < NSEL_) {
        int s;
        if (t < NGLOB_) { s = t * STRIDE_; if (s > KB_ - 1) s = KB_ - 1; }
        else            { int j = t - NGLOB_; s = qid - (NLOCAL_ - 1) + j;
                          s = s < 0 ? 0 : (s > KB_ - 1 ? KB_ - 1 : s); }
        bool valid = (s <= qid);
        bool dup = false;
        for (int jj = 0; jj < t; jj++) {
            int sj;
            if (jj < NGLOB_) { sj = jj * STRIDE_; if (sj > KB_ - 1) sj = KB_ - 1; }
            else             { int j2 = jj - NGLOB_; sj = qid - (NLOCAL_ - 1) + j2;
                               sj = sj < 0 ? 0 : (sj > KB_ - 1 ? KB_ - 1 : sj); }
            if (sj == s) dup = true;
        }
        sel_s[t]  = s;
        keep_s[t] = (valid && !dup) ? 1 : 0;
    }
    if (t < 64) { rowm[t] = -1e30f; rowl[t] = 0.0f; }
    __syncthreads();
    if (t == 0) {
        int c = 0;
        for (int j = 0; j < NSEL_; j++)
            if (keep_s[j]) klist[c++] = sel_s[j];
        kcnt = c;
    }
    __syncthreads();
    const int cnt = kcnt;

    auto load_k = [&](int kblk) {
        const __half* shi = g_khi + ((size_t)(b * S_ + kblk * BS_)) * KVDIM_ + kvh * D_;
        const __half* slo = g_klo + ((size_t)(b * S_ + kblk * BS_)) * KVDIM_ + kvh * D_;
#pragma unroll
        for (int j = 0; j < 8; j++) {
            int idx = t + j * 256;
            int pl = idx >> 10, r = (idx >> 4) & 63, c = idx & 15;
            const __half* src = (pl ? slo : shi) + (size_t)r * KVDIM_ + c * 8;
            __half* dstb = smh + (pl ? KLO_O_ : KHI_O_) + r * 136 + c * 8;
            cp_async16((uint32_t)__cvta_generic_to_shared(dstb), src);
        }
        asm volatile("cp.async.commit_group;\n");
    };
    auto load_v = [&](int kblk) {
        const __half* shi = g_vthi + ((size_t)bkv * D_) * S_ + kblk * BS_;
        const __half* slo = g_vtlo + ((size_t)bkv * D_) * S_ + kblk * BS_;
#pragma unroll
        for (int j = 0; j < 8; j++) {
            int idx = t + j * 256;
            int pl = idx >> 10, r = (idx >> 3) & 127, c = idx & 7;
            const __half* src = (pl ? slo : shi) + (size_t)r * S_ + c * 8;
            __half* dstb = smh + (pl ? VTLO_O_ : VTHI_O_) + r * 72 + c * 8;
            cp_async16((uint32_t)__cvta_generic_to_shared(dstb), src);
        }
        asm volatile("cp.async.commit_group;\n");
    };

    load_k(klist[0]);
    {
        const __half* shi = g_qhi + ((size_t)(b * S_ + qid * BS_)) * QDIM_ + h * D_;
        const __half* slo = g_qlo + ((size_t)(b * S_ + qid * BS_)) * QDIM_ + h * D_;
#pragma unroll
        for (int j = 0; j < 8; j++) {
            int idx = t + j * 256;
            int pl = idx >> 10, r = (idx >> 4) & 63, c = idx & 15;
            const __half* src = (pl ? slo : shi) + (size_t)r * QDIM_ + c * 8;
            __half* dstb = smh + (pl ? QLO_O_ : QHI_O_) + r * 136 + c * 8;
            cp_async16((uint32_t)__cvta_generic_to_shared(dstb), src);
        }
        asm volatile("cp.async.commit_group;\n");
    }

    float o[8][4];
#pragma unroll
    for (int ni = 0; ni < 8; ni++)
#pragma unroll
        for (int c = 0; c < 4; c++) o[ni][c] = 0.0f;

    for (int bi = 0; bi < cnt; bi++) {
        const int kblk = klist[bi];
        const bool diag = (kblk == qid);

        asm volatile("cp.async.wait_group 0;\n" ::: "memory");
        __syncthreads();

        load_v(kblk);

        float sacc[4][4];
#pragma unroll
        for (int ni = 0; ni < 4; ni++)
#pragma unroll
            for (int c = 0; c < 4; c++) sacc[ni][c] = 0.0f;

#pragma unroll
        for (int ks = 0; ks < 8; ks++) {
            const int kb = ks * 8;
            uint32_t ah[4], al[4];
            ah[0] = qhiw[row0 * QLDW_ + kb + tg];
            ah[1] = qhiw[row1 * QLDW_ + kb + tg];
            ah[2] = qhiw[row0 * QLDW_ + kb + tg + 4];
            ah[3] = qhiw[row1 * QLDW_ + kb + tg + 4];
            al[0] = qlow[row0 * QLDW_ + kb + tg];
            al[1] = qlow[row1 * QLDW_ + kb + tg];
            al[2] = qlow[row0 * QLDW_ + kb + tg + 4];
            al[3] = qlow[row1 * QLDW_ + kb + tg + 4];
#pragma unroll
            for (int ni = 0; ni < 4; ni++) {
                const int n = wn + ni * 8 + g;
                uint32_t bh[2], bl[2];
                bh[0] = khiw[n * QLDW_ + kb + tg];
                bh[1] = khiw[n * QLDW_ + kb + tg + 4];
                bl[0] = klow[n * QLDW_ + kb + tg];
                bl[1] = klow[n * QLDW_ + kb + tg + 4];
                mma_f16_k16(sacc[ni], ah, bh);
                mma_f16_k16(sacc[ni], ah, bl);
                mma_f16_k16(sacc[ni], al, bh);
            }
        }

        float pm0 = -1e30f, pm1 = -1e30f;
#pragma unroll
        for (int ni = 0; ni < 4; ni++) {
            const int colb = wn + ni * 8 + 2 * tg;
#pragma unroll
            for (int c = 0; c < 4; c++) {
                const int col = colb + (c & 1);
                const int row = (c < 2) ? row0 : row1;
                float v = sacc[ni][c] * SCALE_;
                if (diag && col > row) v += NEG_;
                sacc[ni][c] = v;
                if (c < 2) pm0 = fmaxf(pm0, v);
                else       pm1 = fmaxf(pm1, v);
            }
        }
        pm0 = fmaxf(pm0, __shfl_xor_sync(0xffffffff, pm0, 1));
        pm0 = fmaxf(pm0, __shfl_xor_sync(0xffffffff, pm0, 2));
        pm1 = fmaxf(pm1, __shfl_xor_sync(0xffffffff, pm1, 1));
        pm1 = fmaxf(pm1, __shfl_xor_sync(0xffffffff, pm1, 2));
        if (tg == 0) {
            wmax[nh * 64 + row0] = pm0;
            wmax[nh * 64 + row1] = pm1;
        }
        __syncthreads();

        float mx0 = fmaxf(fmaxf(wmax[row0], wmax[64 + row0]), rowm[row0]);
        float mx1 = fmaxf(fmaxf(wmax[row1], wmax[64 + row1]), rowm[row1]);
        float ps0 = 0.0f, ps1 = 0.0f;
#pragma unroll
        for (int ni = 0; ni < 4; ni++) {
#pragma unroll
            for (int c = 0; c < 4; c++) {
                float p = __expf(sacc[ni][c] - ((c < 2) ? mx0 : mx1));
                sacc[ni][c] = p;
                if (c < 2) ps0 += p; else ps1 += p;
            }
        }
        ps0 += __shfl_xor_sync(0xffffffff, ps0, 1);
        ps0 += __shfl_xor_sync(0xffffffff, ps0, 2);
        ps1 += __shfl_xor_sync(0xffffffff, ps1, 1);
        ps1 += __shfl_xor_sync(0xffffffff, ps1, 2);
        if (tg == 0) {
            wsum[nh * 64 + row0] = ps0;
            wsum[nh * 64 + row1] = ps1;
        }
        float mxt = 0.0f, ft = 0.0f;
        if (t < 64) {
            mxt = fmaxf(fmaxf(wmax[t], wmax[64 + t]), rowm[t]);
            ft  = __expf(rowm[t] - mxt);
            rowf[t] = ft;
        }
        __syncthreads();

        if (t < 64) {
            rowl[t] = rowl[t] * ft + wsum[t] + wsum[64 + t];
            rowm[t] = mxt;
        }

        {
            float f0 = rowf[row0], f1 = rowf[row1];
#pragma unroll
            for (int ni = 0; ni < 8; ni++) {
                o[ni][0] *= f0; o[ni][1] *= f0;
                o[ni][2] *= f1; o[ni][3] *= f1;
            }
        }
#pragma unroll
        for (int ni = 0; ni < 4; ni++) {
            const int colb = wn + ni * 8 + 2 * tg;
            __half h0, l0, h1, l1;
            split_f16(sacc[ni][0], h0, l0);
            split_f16(sacc[ni][1], h1, l1);
            *(__half2*)(phi + row0 * 72 + colb) = __halves2half2(h0, h1);
            *(__half2*)(plo + row0 * 72 + colb) = __halves2half2(l0, l1);
            split_f16(sacc[ni][2], h0, l0);
            split_f16(sacc[ni][3], h1, l1);
            *(__half2*)(phi + row1 * 72 + colb) = __halves2half2(h0, h1);
            *(__half2*)(plo + row1 * 72 + colb) = __halves2half2(l0, l1);
        }

        asm volatile("cp.async.wait_group 0;\n" ::: "memory");
        __syncthreads();

#pragma unroll
        for (int ks = 0; ks < 4; ks++) {
            const int kb = ks * 8;
            uint32_t ah[4], al[4];
            ah[0] = phiw[row0 * VLDW_ + kb + tg];
            ah[1] = phiw[row1 * VLDW_ + kb + tg];
            ah[2] = phiw[row0 * VLDW_ + kb + tg + 4];
            ah[3] = phiw[row1 * VLDW_ + kb + tg + 4];
            al[0] = plow[row0 * VLDW_ + kb + tg];
            al[1] = plow[row1 * VLDW_ + kb + tg];
            al[2] = plow[row0 * VLDW_ + kb + tg + 4];
            al[3] = plow[row1 * VLDW_ + kb + tg + 4];
#pragma unroll
            for (int ni = 0; ni < 8; ni++) {
                const int n = wn2 + ni * 8 + g;
                uint32_t bh[2], bl[2];
                bh[0] = vhiw[n * VLDW_ + kb + tg];
                bh[1] = vhiw[n * VLDW_ + kb + tg + 4];
                bl[0] = vlow[n * VLDW_ + kb + tg];
                bl[1] = vlow[n * VLDW_ + kb + tg + 4];
                mma_f16_k16(o[ni], ah, bh);
                mma_f16_k16(o[ni], ah, bl);
                mma_f16_k16(o[ni], al, bh);
            }
        }
        __syncthreads();

        if (bi + 1 < cnt) load_k(klist[bi + 1]);
    }

    const float invl0 = 1.0f / rowl[row0];
    const float invl1 = 1.0f / rowl[row1];
    __half* ob0 = g_attn + ((size_t)(b * S_ + qid * BS_ + row0)) * QDIM_ + h * D_;
    __half* ob1 = g_attn + ((size_t)(b * S_ + qid * BS_ + row1)) * QDIM_ + h * D_;
#pragma unroll
    for (int ni = 0; ni < 8; ni++) {
        const int col = wn2 + ni * 8 + 2 * tg;
        __half2 h0 = __floats2half2_rn(o[ni][0] * invl0, o[ni][1] * invl0);
        __half2 h1 = __floats2half2_rn(o[ni][2] * invl1, o[ni][3] * invl1);
        *(__half2*)(ob0 + col) = h0;
        *(__half2*)(ob1 + col) = h1;
    }
}

// ---------------- host launcher ---------------------------------------------
extern "C" void kernel_launch(void* const* d_in, const int* in_sizes, int n_in,
                              void* d_out, int out_size)
{
    const float* X    = (const float*)d_in[0];
    const float* cosp = (const float*)d_in[1];
    const float* sinp = (const float*)d_in[2];
    const float* Wq   = (const float*)d_in[3];
    const float* Wk   = (const float*)d_in[4];
    const float* Wv   = (const float*)d_in[5];
    const float* Wo   = (const float*)d_in[6];
    float* out = (float*)d_out;

    float *qb, *kb, *vb;
    __half *ab, *xh, *wh;
    cudaGetSymbolAddress((void**)&qb, g_q);
    cudaGetSymbolAddress((void**)&kb, g_k);
    cudaGetSymbolAddress((void**)&vb, g_v);
    cudaGetSymbolAddress((void**)&ab, g_attn);
    cudaGetSymbolAddress((void**)&xh, g_xh);
    cudaGetSymbolAddress((void**)&wh, g_wh);

    cudaFuncSetAttribute(attn_kernel,
                         cudaFuncAttributeMaxDynamicSharedMemorySize,
                         AT_SMEM_BYTES);
    cudaFuncSetAttribute(gemm_f16_pipe,
                         cudaFuncAttributeMaxDynamicSharedMemorySize,
                         GSMEM_BYTES);

    const int BIG = 1 << 30;

    // one pass: X + all weights -> fp16
    cvt_all_kernel<<<(CVT_TOT4_ + 255) / 256, 256>>>(X, Wq, Wk, Wv, Wo);

    // Q projection: [8192 x 2048]
    gemm_f16_pipe<<<dim3(QDIM_ / 128, NTOK_ / 128), 256, GSMEM_BYTES>>>(
        xh, wh + WQ_OFF_, qb, qb, BIG, QDIM_, H_);

    // fused K+V projection: weights contiguous [1024 x 2048]; split at col 512
    gemm_f16_pipe<<<dim3(2 * KVDIM_ / 128, NTOK_ / 128), 256, GSMEM_BYTES>>>(
        xh, wh + WK_OFF_, kb, vb, KVDIM_, KVDIM_, H_);

    // RoPE: rotate + write Q/K fp16 split planes
    int rope_total = NTOK_ * (NH_ + NKV_) * (D_ / 2);
    rope_kernel<<<(rope_total + 255) / 256, 256>>>(cosp, sinp);

    // V transpose + split planes
    int vtot = B_ * NKV_ * D_ * S_;
    cvt_v_kernel<<<(vtot + 255) / 256, 256>>>();

    // block-sparse attention (fp16 split planes, writes fp16 to g_attn)
    attn_kernel<<<dim3(KB_, NH_, B_), 256, AT_SMEM_BYTES>>>();

    // O projection
    gemm_f16_pipe<<<dim3(H_ / 128, NTOK_ / 128), 256, GSMEM_BYTES>>>(
        ab, wh + WO_OFF_, out, out, BIG, H_, QDIM_);
}

// round 16
// speedup vs baseline: 1.5225x; 1.0303x over previous
#include <cuda_runtime.h>
#include <cuda_fp16.h>
#include <cstdint>

// ---------------- problem constants ----------------
#define B_      2
#define S_      4096
#define H_      2048
#define NH_     16
#define NKV_    4
#define D_      128
#define BS_     64
#define KB_     (S_ / BS_)
#define NGLOB_  4
#define NLOCAL_ 8
#define NSEL_   (NGLOB_ + NLOCAL_)
#define STRIDE_ 16
#define NTOK_   (B_ * S_)       // 8192
#define QDIM_   (NH_ * D_)      // 2048
#define KVDIM_  (NKV_ * D_)     // 512
#define SCALE_  0.088388347648318447f
#define NEG_    (-1000000000.0f)

// ---------------- scratch ---------------------------------------------------
__device__ float  g_q[(size_t)NTOK_ * QDIM_];
__device__ float  g_k[(size_t)NTOK_ * KVDIM_];
__device__ float  g_v[(size_t)NTOK_ * KVDIM_];
__device__ __half g_attn[(size_t)NTOK_ * QDIM_];      // attention out (fp16)
__device__ __half g_xh[(size_t)NTOK_ * H_];           // X in fp16
// Q/K hi-lo split planes (post-RoPE)
__device__ __half g_qhi[(size_t)NTOK_ * QDIM_];
__device__ __half g_qlo[(size_t)NTOK_ * QDIM_];
__device__ __half g_khi[(size_t)NTOK_ * KVDIM_];
__device__ __half g_klo[(size_t)NTOK_ * KVDIM_];
// V transposed split planes: [(b*NKV+kvh)*D + d][s]
__device__ __half g_vthi[(size_t)B_ * NKV_ * D_ * S_];
__device__ __half g_vtlo[(size_t)B_ * NKV_ * D_ * S_];
// weights fp16: [Wq 4M][Wk 1M][Wv 1M][Wo 4M] halves
#define WQ_OFF_ 0
#define WK_OFF_ ((size_t)QDIM_ * H_)
#define WV_OFF_ (WK_OFF_ + (size_t)KVDIM_ * H_)
#define WO_OFF_ (WV_OFF_ + (size_t)KVDIM_ * H_)
#define WH_HALVES_ (WO_OFF_ + (size_t)QDIM_ * H_)
__device__ __half g_wh[WH_HALVES_];

// ---------------- helpers ---------------------------------------------------
__device__ __forceinline__ void mma_f16_k16(float* c, const uint32_t* a, const uint32_t* b) {
    asm volatile(
        "mma.sync.aligned.m16n8k16.row.col.f32.f16.f16.f32 "
        "{%0,%1,%2,%3}, {%4,%5,%6,%7}, {%8,%9}, {%0,%1,%2,%3};\n"
        : "+f"(c[0]), "+f"(c[1]), "+f"(c[2]), "+f"(c[3])
        : "r"(a[0]), "r"(a[1]), "r"(a[2]), "r"(a[3]), "r"(b[0]), "r"(b[1]));
}
__device__ __forceinline__ void cp_async16(uint32_t saddr, const void* gptr) {
    asm volatile("cp.async.cg.shared.global [%0], [%1], 16;\n"
                 :: "r"(saddr), "l"(gptr));
}
__device__ __forceinline__ void split_f16(float x, __half& hi, __half& lo) {
    hi = __float2half_rn(x);
    lo = __float2half_rn(x - __half2float(hi));
}
__device__ __forceinline__ void ldsm_x4(uint32_t& r0, uint32_t& r1,
                                        uint32_t& r2, uint32_t& r3, uint32_t addr) {
    asm volatile("ldmatrix.sync.aligned.m8n8.x4.shared.b16 {%0,%1,%2,%3}, [%4];"
                 : "=r"(r0), "=r"(r1), "=r"(r2), "=r"(r3) : "r"(addr));
}

// ---------------- merged fp32 -> fp16 conversion ----------------------------
#define CVT_X4_   (NTOK_ * (H_ / 4))
#define CVT_WQ4_  (QDIM_ * (H_ / 4))
#define CVT_WK4_  (KVDIM_ * (H_ / 4))
#define CVT_TOT4_ (CVT_X4_ + CVT_WQ4_ + 2 * CVT_WK4_ + CVT_WQ4_)

__global__ void cvt_all_kernel(const float* __restrict__ X,
                               const float* __restrict__ Wq,
                               const float* __restrict__ Wk,
                               const float* __restrict__ Wv,
                               const float* __restrict__ Wo)
{
    int i = blockIdx.x * blockDim.x + threadIdx.x;
    if (i >= CVT_TOT4_) return;

    const float4* src;
    uint2* dst;
    if (i < CVT_X4_) {
        src = (const float4*)X + i;
        dst = (uint2*)g_xh + i;
    } else if (i < CVT_X4_ + CVT_WQ4_) {
        int j = i - CVT_X4_;
        src = (const float4*)Wq + j;
        dst = (uint2*)(g_wh + WQ_OFF_) + j;
    } else if (i < CVT_X4_ + CVT_WQ4_ + CVT_WK4_) {
        int j = i - CVT_X4_ - CVT_WQ4_;
        src = (const float4*)Wk + j;
        dst = (uint2*)(g_wh + WK_OFF_) + j;
    } else if (i < CVT_X4_ + CVT_WQ4_ + 2 * CVT_WK4_) {
        int j = i - CVT_X4_ - CVT_WQ4_ - CVT_WK4_;
        src = (const float4*)Wv + j;
        dst = (uint2*)(g_wh + WV_OFF_) + j;
    } else {
        int j = i - CVT_X4_ - CVT_WQ4_ - 2 * CVT_WK4_;
        src = (const float4*)Wo + j;
        dst = (uint2*)(g_wh + WO_OFF_) + j;
    }
    float4 v = *src;
    __half2 h0 = __floats2half2_rn(v.x, v.y);
    __half2 h1 = __floats2half2_rn(v.z, v.w);
    uint2 o;
    o.x = *(uint32_t*)&h0;
    o.y = *(uint32_t*)&h1;
    *dst = o;
}

// ---------------- pipelined fp16 GEMM (ldmatrix + 5 stages) -----------------
#define BKH_  32
#define LDHW_ 20
#define GSTG_ 5
#define ST_WORDS_ (2 * 128 * LDHW_)
#define GSMEM_BYTES (GSTG_ * ST_WORDS_ * 4)      // 102400

__global__ void __launch_bounds__(256, 2)
gemm_f16_pipe(const __half* __restrict__ A, const __half* __restrict__ B,
              float* __restrict__ C0, float* __restrict__ C1,
              int Nsplit, int ldc, int K)
{
    extern __shared__ uint32_t smg[];

    const size_t bm = (size_t)blockIdx.y * 128;
    const size_t bn = (size_t)blockIdx.x * 128;
    const int t = threadIdx.x;
    const int lane = t & 31, warp = t >> 5;
    const int wm = (warp >> 2) * 64;
    const int wn = (warp & 3) * 32;
    const int g  = lane >> 2, tg = lane & 3;

    const int arow = lane & 15;
    const int ak4  = (lane >> 4) << 2;
    const int brow = (lane & 7) + ((lane >> 4) << 3);
    const int bk4  = ((lane >> 3) & 1) << 2;

    const uint32_t smg_u32 = (uint32_t)__cvta_generic_to_shared(smg);

    float acc[4][4][4];
#pragma unroll
    for (int mi = 0; mi < 4; mi++)
#pragma unroll
        for (int ni = 0; ni < 4; ni++)
#pragma unroll
            for (int c = 0; c < 4; c++) acc[mi][ni][c] = 0.0f;

    auto load_stage = [&](int s, int i) {
        uint32_t* as = smg + s * ST_WORDS_;
        uint32_t* bs = as + 128 * LDHW_;
        const int k0 = i * BKH_;
#pragma unroll
        for (int j = 0; j < 2; j++) {
            int idx = t + j * 256;
            int row = idx >> 2, c4 = idx & 3;
            uint32_t sa = (uint32_t)__cvta_generic_to_shared(&as[row * LDHW_ + c4 * 4]);
            cp_async16(sa, A + (bm + row) * (size_t)K + k0 + c4 * 8);
            uint32_t sb = (uint32_t)__cvta_generic_to_shared(&bs[row * LDHW_ + c4 * 4]);
            cp_async16(sb, B + (bn + row) * (size_t)K + k0 + c4 * 8);
        }
        asm volatile("cp.async.commit_group;\n");
    };

    auto compute_stage = [&](int s) {
        const uint32_t a_st = smg_u32 + (s * ST_WORDS_) * 4;
        const uint32_t b_st = a_st + (128 * LDHW_) * 4;
#pragma unroll
        for (int kk = 0; kk < 2; kk++) {
            const int kb = kk * 8;
            uint32_t a[4][4];
#pragma unroll
            for (int mi = 0; mi < 4; mi++) {
                uint32_t addr = a_st + ((wm + mi * 16 + arow) * LDHW_ + kb + ak4) * 4;
                ldsm_x4(a[mi][0], a[mi][1], a[mi][2], a[mi][3], addr);
            }
            uint32_t bf[4][2];
#pragma unroll
            for (int np = 0; np < 2; np++) {
                uint32_t addr = b_st + ((wn + np * 16 + brow) * LDHW_ + kb + bk4) * 4;
                ldsm_x4(bf[2 * np][0], bf[2 * np][1],
                        bf[2 * np + 1][0], bf[2 * np + 1][1], addr);
            }
#pragma unroll
            for (int mi = 0; mi < 4; mi++)
#pragma unroll
                for (int ni = 0; ni < 4; ni++)
                    mma_f16_k16(acc[mi][ni], a[mi], bf[ni]);
        }
    };

    const int niter = K / BKH_;
    load_stage(0, 0);
    load_stage(1, 1);
    load_stage(2, 2);
    load_stage(3, 3);

    for (int i = 0; i < niter - 1; i++) {
        asm volatile("cp.async.wait_group 3;\n" ::: "memory");
        __syncthreads();
        if (i + 4 < niter) load_stage((i + 4) % GSTG_, i + 4);
        compute_stage(i % GSTG_);
    }
    asm volatile("cp.async.wait_group 0;\n" ::: "memory");
    __syncthreads();
    compute_stage((niter - 1) % GSTG_);

    float* C = C0;
    int cb = (int)bn;
    if (cb >= Nsplit) { C = C1; cb -= Nsplit; }

#pragma unroll
    for (int mi = 0; mi < 4; mi++) {
        const size_t row = bm + wm + mi * 16 + g;
#pragma unroll
        for (int ni = 0; ni < 4; ni++) {
            const int col = cb + wn + ni * 8 + 2 * tg;
            float* cp0 = C + row * ldc + col;
            float* cp1 = cp0 + (size_t)8 * ldc;
            *(float2*)cp0 = make_float2(acc[mi][ni][0], acc[mi][ni][1]);
            *(float2*)cp1 = make_float2(acc[mi][ni][2], acc[mi][ni][3]);
        }
    }
}

// ---------------- RoPE: rotate + fp16 hi/lo split to planes -----------------
__global__ void rope_kernel(const float* __restrict__ cosp,
                            const float* __restrict__ sinp)
{
    int idx = blockIdx.x * blockDim.x + threadIdx.x;
    const int total = NTOK_ * (NH_ + NKV_) * (D_ / 2);
    if (idx >= total) return;

    int d    = idx % (D_ / 2);
    int rest = idx / (D_ / 2);
    int h    = rest % (NH_ + NKV_);
    int tok  = rest / (NH_ + NKV_);

    float c1 = cosp[(size_t)tok * D_ + d];
    float s1 = sinp[(size_t)tok * D_ + d];
    float c2 = cosp[(size_t)tok * D_ + d + D_ / 2];
    float s2 = sinp[(size_t)tok * D_ + d + D_ / 2];

    const float* buf;
    __half *hip, *lop;
    size_t off;
    if (h < NH_) {
        off = (size_t)tok * QDIM_ + h * D_;
        buf = g_q + off; hip = g_qhi + off; lop = g_qlo + off;
    } else {
        off = (size_t)tok * KVDIM_ + (h - NH_) * D_;
        buf = g_k + off; hip = g_khi + off; lop = g_klo + off;
    }

    float x1 = buf[d];
    float x2 = buf[d + D_ / 2];
    float o1 = x1 * c1 - x2 * s1;
    float o2 = x2 * c2 + x1 * s2;

    __half h1v, l1v, h2v, l2v;
    split_f16(o1, h1v, l1v);
    split_f16(o2, h2v, l2v);
    hip[d] = h1v;            lop[d] = l1v;
    hip[d + D_ / 2] = h2v;   lop[d + D_ / 2] = l2v;
}

// ---------------- V transpose + split:  vt[(bkv*D+d)*S + s] -----------------
__global__ void cvt_v_kernel()
{
    int idx = blockIdx.x * blockDim.x + threadIdx.x;
    const int total = B_ * NKV_ * D_ * S_;
    if (idx >= total) return;
    int s    = idx % S_;
    int rest = idx / S_;
    int d    = rest % D_;
    int bkv  = rest / D_;
    int b    = bkv / NKV_;
    int kvh  = bkv % NKV_;
    float x = g_v[((size_t)(b * S_ + s)) * KVDIM_ + kvh * D_ + d];
    __half hi, lo;
    split_f16(x, hi, lo);
    g_vthi[idx] = hi;
    g_vtlo[idx] = lo;
}

// ---------------- block-sparse attention (fp16 planes + ldmatrix) -----------
#define QLDH_  136     // Q/K row stride in halves
#define VLDH_  72      // VT/P row stride in halves
#define QHI_O_ 0
#define QLO_O_ 8704
#define KHI_O_ 17408
#define KLO_O_ 26112
#define VTHI_O_ 34816
#define VTLO_O_ 44032
#define SMH_HALVES_ 53248
#define AT_STAT_FLOATS (128 + 128 + 3 * 64)
#define AT_SMEM_BYTES (SMH_HALVES_ * 2 + AT_STAT_FLOATS * 4)   // 108288

__global__ void __launch_bounds__(256, 2)
attn_kernel()
{
    extern __shared__ __half smh[];
    float* stat = (float*)(smh + SMH_HALVES_);
    float* wmax = stat;
    float* wsum = wmax + 128;
    float* rowm = wsum + 128;
    float* rowl = rowm + 64;
    float* rowf = rowl + 64;
    __shared__ int sel_s[NSEL_];
    __shared__ int keep_s[NSEL_];
    __shared__ int klist[NSEL_];
    __shared__ int kcnt;

    __half* phi = smh + KHI_O_;        // P hi aliases K hi
    __half* plo = smh + KLO_O_;        // P lo aliases K lo

    const uint32_t smh_u32 = (uint32_t)__cvta_generic_to_shared(smh);
    const uint32_t qhi_st = smh_u32 + QHI_O_ * 2;
    const uint32_t qlo_st = smh_u32 + QLO_O_ * 2;
    const uint32_t khi_st = smh_u32 + KHI_O_ * 2;
    const uint32_t klo_st = smh_u32 + KLO_O_ * 2;
    const uint32_t vhi_st = smh_u32 + VTHI_O_ * 2;
    const uint32_t vlo_st = smh_u32 + VTLO_O_ * 2;
    const uint32_t phi_st = khi_st;
    const uint32_t plo_st = klo_st;

    const int qid = blockIdx.x;
    const int h   = blockIdx.y;
    const int b   = blockIdx.z;
    const int t   = threadIdx.x;
    const int kvh = h / (NH_ / NKV_);
    const int bkv = b * NKV_ + kvh;

    const int warp = t >> 5, lane = t & 31;
    const int g  = lane >> 2;
    const int tg = lane & 3;
    const int wm  = (warp >> 1) * 16;
    const int nh  = warp & 1;
    const int wn  = nh * 32;
    const int wn2 = nh * 64;
    const int row0 = wm + g;
    const int row1 = wm + g + 8;

    // ldmatrix lane address components (halves)
    const int arow = lane & 15;
    const int ak8  = (lane >> 4) << 3;
    const int brow = (lane & 7) + ((lane >> 4) << 3);
    const int bk8  = ((lane >> 3) & 1) << 3;

    if (t < NSEL_) {
        int s;
        if (t < NGLOB_) { s = t * STRIDE_; if (s > KB_ - 1) s = KB_ - 1; }
        else            { int j = t - NGLOB_; s = qid - (NLOCAL_ - 1) + j;
                          s = s < 0 ? 0 : (s > KB_ - 1 ? KB_ - 1 : s); }
        bool valid = (s <= qid);
        bool dup = false;
        for (int jj = 0; jj < t; jj++) {
            int sj;
            if (jj < NGLOB_) { sj = jj * STRIDE_; if (sj > KB_ - 1) sj = KB_ - 1; }
            else             { int j2 = jj - NGLOB_; sj = qid - (NLOCAL_ - 1) + j2;
                               sj = sj < 0 ? 0 : (sj > KB_ - 1 ? KB_ - 1 : sj); }
            if (sj == s) dup = true;
        }
        sel_s[t]  = s;
        keep_s[t] = (valid && !dup) ? 1 : 0;
    }
    if (t < 64) { rowm[t] = -1e30f; rowl[t] = 0.0f; }
    __syncthreads();
    if (t == 0) {
        int c = 0;
        for (int j = 0; j < NSEL_; j++)
            if (keep_s[j]) klist[c++] = sel_s[j];
        kcnt = c;
    }
    __syncthreads();
    const int cnt = kcnt;

    auto load_k = [&](int kblk) {
        const __half* shi = g_khi + ((size_t)(b * S_ + kblk * BS_)) * KVDIM_ + kvh * D_;
        const __half* slo = g_klo + ((size_t)(b * S_ + kblk * BS_)) * KVDIM_ + kvh * D_;
#pragma unroll
        for (int j = 0; j < 8; j++) {
            int idx = t + j * 256;
            int pl = idx >> 10, r = (idx >> 4) & 63, c = idx & 15;
            const __half* src = (pl ? slo : shi) + (size_t)r * KVDIM_ + c * 8;
            __half* dstb = smh + (pl ? KLO_O_ : KHI_O_) + r * QLDH_ + c * 8;
            cp_async16((uint32_t)__cvta_generic_to_shared(dstb), src);
        }
        asm volatile("cp.async.commit_group;\n");
    };
    auto load_v = [&](int kblk) {
        const __half* shi = g_vthi + ((size_t)bkv * D_) * S_ + kblk * BS_;
        const __half* slo = g_vtlo + ((size_t)bkv * D_) * S_ + kblk * BS_;
#pragma unroll
        for (int j = 0; j < 8; j++) {
            int idx = t + j * 256;
            int pl = idx >> 10, r = (idx >> 3) & 127, c = idx & 7;
            const __half* src = (pl ? slo : shi) + (size_t)r * S_ + c * 8;
            __half* dstb = smh + (pl ? VTLO_O_ : VTHI_O_) + r * VLDH_ + c * 8;
            cp_async16((uint32_t)__cvta_generic_to_shared(dstb), src);
        }
        asm volatile("cp.async.commit_group;\n");
    };

    load_k(klist[0]);
    {
        const __half* shi = g_qhi + ((size_t)(b * S_ + qid * BS_)) * QDIM_ + h * D_;
        const __half* slo = g_qlo + ((size_t)(b * S_ + qid * BS_)) * QDIM_ + h * D_;
#pragma unroll
        for (int j = 0; j < 8; j++) {
            int idx = t + j * 256;
            int pl = idx >> 10, r = (idx >> 4) & 63, c = idx & 15;
            const __half* src = (pl ? slo : shi) + (size_t)r * QDIM_ + c * 8;
            __half* dstb = smh + (pl ? QLO_O_ : QHI_O_) + r * QLDH_ + c * 8;
            cp_async16((uint32_t)__cvta_generic_to_shared(dstb), src);
        }
        asm volatile("cp.async.commit_group;\n");
    }

    float o[8][4];
#pragma unroll
    for (int ni = 0; ni < 8; ni++)
#pragma unroll
        for (int c = 0; c < 4; c++) o[ni][c] = 0.0f;

    for (int bi = 0; bi < cnt; bi++) {
        const int kblk = klist[bi];
        const bool diag = (kblk == qid);

        asm volatile("cp.async.wait_group 0;\n" ::: "memory");
        __syncthreads();

        load_v(kblk);

        // ---- S = Q @ K^T : 3-term fp16 split, ldmatrix fragments
        float sacc[4][4];
#pragma unroll
        for (int ni = 0; ni < 4; ni++)
#pragma unroll
            for (int c = 0; c < 4; c++) sacc[ni][c] = 0.0f;

#pragma unroll
        for (int ks = 0; ks < 8; ks++) {
            const int kh = ks * 16;      // k offset in halves
            uint32_t ah[4], al[4];
            ldsm_x4(ah[0], ah[1], ah[2], ah[3],
                    qhi_st + ((wm + arow) * QLDH_ + kh + ak8) * 2);
            ldsm_x4(al[0], al[1], al[2], al[3],
                    qlo_st + ((wm + arow) * QLDH_ + kh + ak8) * 2);
            uint32_t bh[4][2], bl[4][2];
#pragma unroll
            for (int np = 0; np < 2; np++) {
                ldsm_x4(bh[2 * np][0], bh[2 * np][1], bh[2 * np + 1][0], bh[2 * np + 1][1],
                        khi_st + ((wn + np * 16 + brow) * QLDH_ + kh + bk8) * 2);
                ldsm_x4(bl[2 * np][0], bl[2 * np][1], bl[2 * np + 1][0], bl[2 * np + 1][1],
                        klo_st + ((wn + np * 16 + brow) * QLDH_ + kh + bk8) * 2);
            }
#pragma unroll
            for (int ni = 0; ni < 4; ni++) {
                mma_f16_k16(sacc[ni], ah, bh[ni]);
                mma_f16_k16(sacc[ni], ah, bl[ni]);
                mma_f16_k16(sacc[ni], al, bh[ni]);
            }
        }

        // ---- scale + mask + partial max
        float pm0 = -1e30f, pm1 = -1e30f;
#pragma unroll
        for (int ni = 0; ni < 4; ni++) {
            const int colb = wn + ni * 8 + 2 * tg;
#pragma unroll
            for (int c = 0; c < 4; c++) {
                const int col = colb + (c & 1);
                const int row = (c < 2) ? row0 : row1;
                float v = sacc[ni][c] * SCALE_;
                if (diag && col > row) v += NEG_;
                sacc[ni][c] = v;
                if (c < 2) pm0 = fmaxf(pm0, v);
                else       pm1 = fmaxf(pm1, v);
            }
        }
        pm0 = fmaxf(pm0, __shfl_xor_sync(0xffffffff, pm0, 1));
        pm0 = fmaxf(pm0, __shfl_xor_sync(0xffffffff, pm0, 2));
        pm1 = fmaxf(pm1, __shfl_xor_sync(0xffffffff, pm1, 1));
        pm1 = fmaxf(pm1, __shfl_xor_sync(0xffffffff, pm1, 2));
        if (tg == 0) {
            wmax[nh * 64 + row0] = pm0;
            wmax[nh * 64 + row1] = pm1;
        }
        __syncthreads();

        float mx0 = fmaxf(fmaxf(wmax[row0], wmax[64 + row0]), rowm[row0]);
        float mx1 = fmaxf(fmaxf(wmax[row1], wmax[64 + row1]), rowm[row1]);
        float ps0 = 0.0f, ps1 = 0.0f;
#pragma unroll
        for (int ni = 0; ni < 4; ni++) {
#pragma unroll
            for (int c = 0; c < 4; c++) {
                float p = __expf(sacc[ni][c] - ((c < 2) ? mx0 : mx1));
                sacc[ni][c] = p;
                if (c < 2) ps0 += p; else ps1 += p;
            }
        }
        ps0 += __shfl_xor_sync(0xffffffff, ps0, 1);
        ps0 += __shfl_xor_sync(0xffffffff, ps0, 2);
        ps1 += __shfl_xor_sync(0xffffffff, ps1, 1);
        ps1 += __shfl_xor_sync(0xffffffff, ps1, 2);
        if (tg == 0) {
            wsum[nh * 64 + row0] = ps0;
            wsum[nh * 64 + row1] = ps1;
        }
        float mxt = 0.0f, ft = 0.0f;
        if (t < 64) {
            mxt = fmaxf(fmaxf(wmax[t], wmax[64 + t]), rowm[t]);
            ft  = __expf(rowm[t] - mxt);
            rowf[t] = ft;
        }
        __syncthreads();

        if (t < 64) {
            rowl[t] = rowl[t] * ft + wsum[t] + wsum[64 + t];
            rowm[t] = mxt;
        }

        // rescale O; split P into hi/lo planes (aliasing K)
        {
            float f0 = rowf[row0], f1 = rowf[row1];
#pragma unroll
            for (int ni = 0; ni < 8; ni++) {
                o[ni][0] *= f0; o[ni][1] *= f0;
                o[ni][2] *= f1; o[ni][3] *= f1;
            }
        }
#pragma unroll
        for (int ni = 0; ni < 4; ni++) {
            const int colb = wn + ni * 8 + 2 * tg;
            __half h0, l0, h1, l1;
            split_f16(sacc[ni][0], h0, l0);
            split_f16(sacc[ni][1], h1, l1);
            *(__half2*)(phi + row0 * VLDH_ + colb) = __halves2half2(h0, h1);
            *(__half2*)(plo + row0 * VLDH_ + colb) = __halves2half2(l0, l1);
            split_f16(sacc[ni][2], h0, l0);
            split_f16(sacc[ni][3], h1, l1);
            *(__half2*)(phi + row1 * VLDH_ + colb) = __halves2half2(h0, h1);
            *(__half2*)(plo + row1 * VLDH_ + colb) = __halves2half2(l0, l1);
        }

        asm volatile("cp.async.wait_group 0;\n" ::: "memory");
        __syncthreads();

        // ---- O += P @ V : 3-term fp16 split, ldmatrix fragments
#pragma unroll
        for (int ks = 0; ks < 4; ks++) {
            const int kh = ks * 16;
            uint32_t ah[4], al[4];
            ldsm_x4(ah[0], ah[1], ah[2], ah[3],
                    phi_st + ((wm + arow) * VLDH_ + kh + ak8) * 2);
            ldsm_x4(al[0], al[1], al[2], al[3],
                    plo_st + ((wm + arow) * VLDH_ + kh + ak8) * 2);
            uint32_t bh[8][2], bl[8][2];
#pragma unroll
            for (int np = 0; np < 4; np++) {
                ldsm_x4(bh[2 * np][0], bh[2 * np][1], bh[2 * np + 1][0], bh[2 * np + 1][1],
                        vhi_st + ((wn2 + np * 16 + brow) * VLDH_ + kh + bk8) * 2);
                ldsm_x4(bl[2 * np][0], bl[2 * np][1], bl[2 * np + 1][0], bl[2 * np + 1][1],
                        vlo_st + ((wn2 + np * 16 + brow) * VLDH_ + kh + bk8) * 2);
            }
#pragma unroll
            for (int ni = 0; ni < 8; ni++) {
                mma_f16_k16(o[ni], ah, bh[ni]);
                mma_f16_k16(o[ni], ah, bl[ni]);
                mma_f16_k16(o[ni], al, bh[ni]);
            }
        }
        __syncthreads();

        if (bi + 1 < cnt) load_k(klist[bi + 1]);
    }

    const float invl0 = 1.0f / rowl[row0];
    const float invl1 = 1.0f / rowl[row1];
    __half* ob0 = g_attn + ((size_t)(b * S_ + qid * BS_ + row0)) * QDIM_ + h * D_;
    __half* ob1 = g_attn + ((size_t)(b * S_ + qid * BS_ + row1)) * QDIM_ + h * D_;
#pragma unroll
    for (int ni = 0; ni < 8; ni++) {
        const int col = wn2 + ni * 8 + 2 * tg;
        __half2 h0 = __floats2half2_rn(o[ni][0] * invl0, o[ni][1] * invl0);
        __half2 h1 = __floats2half2_rn(o[ni][2] * invl1, o[ni][3] * invl1);
        *(__half2*)(ob0 + col) = h0;
        *(__half2*)(ob1 + col) = h1;
    }
}

// ---------------- host launcher ---------------------------------------------
extern "C" void kernel_launch(void* const* d_in, const int* in_sizes, int n_in,
                              void* d_out, int out_size)
{
    const float* X    = (const float*)d_in[0];
    const float* cosp = (const float*)d_in[1];
    const float* sinp = (const float*)d_in[2];
    const float* Wq   = (const float*)d_in[3];
    const float* Wk   = (const float*)d_in[4];
    const float* Wv   = (const float*)d_in[5];
    const float* Wo   = (const float*)d_in[6];
    float* out = (float*)d_out;

    float *qb, *kb, *vb;
    __half *ab, *xh, *wh;
    cudaGetSymbolAddress((void**)&qb, g_q);
    cudaGetSymbolAddress((void**)&kb, g_k);
    cudaGetSymbolAddress((void**)&vb, g_v);
    cudaGetSymbolAddress((void**)&ab, g_attn);
    cudaGetSymbolAddress((void**)&xh, g_xh);
    cudaGetSymbolAddress((void**)&wh, g_wh);

    cudaFuncSetAttribute(attn_kernel,
                         cudaFuncAttributeMaxDynamicSharedMemorySize,
                         AT_SMEM_BYTES);
    cudaFuncSetAttribute(gemm_f16_pipe,
                         cudaFuncAttributeMaxDynamicSharedMemorySize,
                         GSMEM_BYTES);

    const int BIG = 1 << 30;

    // one pass: X + all weights -> fp16
    cvt_all_kernel<<<(CVT_TOT4_ + 255) / 256, 256>>>(X, Wq, Wk, Wv, Wo);

    // Q projection: [8192 x 2048]
    gemm_f16_pipe<<<dim3(QDIM_ / 128, NTOK_ / 128), 256, GSMEM_BYTES>>>(
        xh, wh + WQ_OFF_, qb, qb, BIG, QDIM_, H_);

    // fused K+V projection: weights contiguous [1024 x 2048]; split at col 512
    gemm_f16_pipe<<<dim3(2 * KVDIM_ / 128, NTOK_ / 128), 256, GSMEM_BYTES>>>(
        xh, wh + WK_OFF_, kb, vb, KVDIM_, KVDIM_, H_);

    // RoPE: rotate + write Q/K fp16 split planes
    int rope_total = NTOK_ * (NH_ + NKV_) * (D_ / 2);
    rope_kernel<<<(rope_total + 255) / 256, 256>>>(cosp, sinp);

    // V transpose + split planes
    int vtot = B_ * NKV_ * D_ * S_;
    cvt_v_kernel<<<(vtot + 255) / 256, 256>>>();

    // block-sparse attention (fp16 split planes, writes fp16 to g_attn)
    attn_kernel<<<dim3(KB_, NH_, B_), 256, AT_SMEM_BYTES>>>();

    // O projection
    gemm_f16_pipe<<<dim3(H_ / 128, NTOK_ / 128), 256, GSMEM_BYTES>>>(
        ab, wh + WO_OFF_, out, out, BIG, H_, QDIM_);
}

// round 17
// speedup vs baseline: 1.6618x; 1.0915x over previous
#include <cuda_runtime.h>
#include <cuda_fp16.h>
#include <cstdint>

// ---------------- problem constants ----------------
#define B_      2
#define S_      4096
#define H_      2048
#define NH_     16
#define NKV_    4
#define D_      128
#define BS_     64
#define KB_     (S_ / BS_)
#define NGLOB_  4
#define NLOCAL_ 8
#define NSEL_   (NGLOB_ + NLOCAL_)
#define STRIDE_ 16
#define NTOK_   (B_ * S_)       // 8192
#define QDIM_   (NH_ * D_)      // 2048
#define KVDIM_  (NKV_ * D_)     // 512
#define SCALE_  0.088388347648318447f
#define NEG_    (-1000000000.0f)

// ---------------- scratch ---------------------------------------------------
__device__ float  g_q[(size_t)NTOK_ * QDIM_];
__device__ float  g_k[(size_t)NTOK_ * KVDIM_];
__device__ float  g_v[(size_t)NTOK_ * KVDIM_];
__device__ __half g_attn[(size_t)NTOK_ * QDIM_];      // attention out (fp16)
__device__ __half g_xh[(size_t)NTOK_ * H_];           // X in fp16
// Q/K hi-lo split planes (post-RoPE)
__device__ __half g_qhi[(size_t)NTOK_ * QDIM_];
__device__ __half g_qlo[(size_t)NTOK_ * QDIM_];
__device__ __half g_khi[(size_t)NTOK_ * KVDIM_];
__device__ __half g_klo[(size_t)NTOK_ * KVDIM_];
// V transposed split planes: [(b*NKV+kvh)*D + d][s]
__device__ __half g_vthi[(size_t)B_ * NKV_ * D_ * S_];
__device__ __half g_vtlo[(size_t)B_ * NKV_ * D_ * S_];
// weights fp16: [Wq 4M][Wk 1M][Wv 1M][Wo 4M] halves
#define WQ_OFF_ 0
#define WK_OFF_ ((size_t)QDIM_ * H_)
#define WV_OFF_ (WK_OFF_ + (size_t)KVDIM_ * H_)
#define WO_OFF_ (WV_OFF_ + (size_t)KVDIM_ * H_)
#define WH_HALVES_ (WO_OFF_ + (size_t)QDIM_ * H_)
__device__ __half g_wh[WH_HALVES_];

// ---------------- helpers ---------------------------------------------------
__device__ __forceinline__ void mma_f16_k16(float* c, const uint32_t* a, const uint32_t* b) {
    asm volatile(
        "mma.sync.aligned.m16n8k16.row.col.f32.f16.f16.f32 "
        "{%0,%1,%2,%3}, {%4,%5,%6,%7}, {%8,%9}, {%0,%1,%2,%3};\n"
        : "+f"(c[0]), "+f"(c[1]), "+f"(c[2]), "+f"(c[3])
        : "r"(a[0]), "r"(a[1]), "r"(a[2]), "r"(a[3]), "r"(b[0]), "r"(b[1]));
}
__device__ __forceinline__ void cp_async16(uint32_t saddr, const void* gptr) {
    asm volatile("cp.async.cg.shared.global [%0], [%1], 16;\n"
                 :: "r"(saddr), "l"(gptr));
}
__device__ __forceinline__ void split_f16(float x, __half& hi, __half& lo) {
    hi = __float2half_rn(x);
    lo = __float2half_rn(x - __half2float(hi));
}
__device__ __forceinline__ void ldsm_x4(uint32_t& r0, uint32_t& r1,
                                        uint32_t& r2, uint32_t& r3, uint32_t addr) {
    asm volatile("ldmatrix.sync.aligned.m8n8.x4.shared.b16 {%0,%1,%2,%3}, [%4];"
                 : "=r"(r0), "=r"(r1), "=r"(r2), "=r"(r3) : "r"(addr));
}

// ---------------- merged fp32 -> fp16 conversion ----------------------------
#define CVT_X4_   (NTOK_ * (H_ / 4))
#define CVT_WQ4_  (QDIM_ * (H_ / 4))
#define CVT_WK4_  (KVDIM_ * (H_ / 4))
#define CVT_TOT4_ (CVT_X4_ + CVT_WQ4_ + 2 * CVT_WK4_ + CVT_WQ4_)

__global__ void cvt_all_kernel(const float* __restrict__ X,
                               const float* __restrict__ Wq,
                               const float* __restrict__ Wk,
                               const float* __restrict__ Wv,
                               const float* __restrict__ Wo)
{
    int i = blockIdx.x * blockDim.x + threadIdx.x;
    if (i >= CVT_TOT4_) return;

    const float4* src;
    uint2* dst;
    if (i < CVT_X4_) {
        src = (const float4*)X + i;
        dst = (uint2*)g_xh + i;
    } else if (i < CVT_X4_ + CVT_WQ4_) {
        int j = i - CVT_X4_;
        src = (const float4*)Wq + j;
        dst = (uint2*)(g_wh + WQ_OFF_) + j;
    } else if (i < CVT_X4_ + CVT_WQ4_ + CVT_WK4_) {
        int j = i - CVT_X4_ - CVT_WQ4_;
        src = (const float4*)Wk + j;
        dst = (uint2*)(g_wh + WK_OFF_) + j;
    } else if (i < CVT_X4_ + CVT_WQ4_ + 2 * CVT_WK4_) {
        int j = i - CVT_X4_ - CVT_WQ4_ - CVT_WK4_;
        src = (const float4*)Wv + j;
        dst = (uint2*)(g_wh + WV_OFF_) + j;
    } else {
        int j = i - CVT_X4_ - CVT_WQ4_ - 2 * CVT_WK4_;
        src = (const float4*)Wo + j;
        dst = (uint2*)(g_wh + WO_OFF_) + j;
    }
    float4 v = *src;
    __half2 h0 = __floats2half2_rn(v.x, v.y);
    __half2 h1 = __floats2half2_rn(v.z, v.w);
    uint2 o;
    o.x = *(uint32_t*)&h0;
    o.y = *(uint32_t*)&h1;
    *dst = o;
}

// ---------------- pipelined fp16 GEMM (ldmatrix, BK=64, 3 stages) -----------
#define BKH_  64
#define LDHW_ 36                                 // words per smem row (72 halves)
#define GSTG_ 3
#define ST_WORDS_ (2 * 128 * LDHW_)              // A+B per stage = 9216 words
#define GSMEM_BYTES (GSTG_ * ST_WORDS_ * 4)      // 110592

__global__ void __launch_bounds__(256, 2)
gemm_f16_pipe(const __half* __restrict__ A, const __half* __restrict__ B,
              float* __restrict__ C0, float* __restrict__ C1,
              int Nsplit, int ldc, int K)
{
    extern __shared__ uint32_t smg[];

    const size_t bm = (size_t)blockIdx.y * 128;
    const size_t bn = (size_t)blockIdx.x * 128;
    const int t = threadIdx.x;
    const int lane = t & 31, warp = t >> 5;
    const int wm = (warp >> 2) * 64;
    const int wn = (warp & 3) * 32;
    const int g  = lane >> 2, tg = lane & 3;

    const int arow = lane & 15;
    const int ak4  = (lane >> 4) << 2;
    const int brow = (lane & 7) + ((lane >> 4) << 3);
    const int bk4  = ((lane >> 3) & 1) << 2;

    const uint32_t smg_u32 = (uint32_t)__cvta_generic_to_shared(smg);

    float acc[4][4][4];
#pragma unroll
    for (int mi = 0; mi < 4; mi++)
#pragma unroll
        for (int ni = 0; ni < 4; ni++)
#pragma unroll
            for (int c = 0; c < 4; c++) acc[mi][ni][c] = 0.0f;

    // per stage: A 128 rows x 8 chunks + B 128 rows x 8 chunks = 2048 chunks
    auto load_stage = [&](int s, int i) {
        uint32_t* as = smg + s * ST_WORDS_;
        uint32_t* bs = as + 128 * LDHW_;
        const int k0 = i * BKH_;
#pragma unroll
        for (int j = 0; j < 4; j++) {
            int idx = t + j * 256;
            int row = idx >> 3, c8 = idx & 7;
            uint32_t sa = (uint32_t)__cvta_generic_to_shared(&as[row * LDHW_ + c8 * 4]);
            cp_async16(sa, A + (bm + row) * (size_t)K + k0 + c8 * 8);
            uint32_t sb = (uint32_t)__cvta_generic_to_shared(&bs[row * LDHW_ + c8 * 4]);
            cp_async16(sb, B + (bn + row) * (size_t)K + k0 + c8 * 8);
        }
        asm volatile("cp.async.commit_group;\n");
    };

    auto compute_stage = [&](int s) {
        const uint32_t a_st = smg_u32 + (s * ST_WORDS_) * 4;
        const uint32_t b_st = a_st + (128 * LDHW_) * 4;
#pragma unroll
        for (int kk = 0; kk < 4; kk++) {
            const int kb = kk * 8;               // word offset (16 halves)
            uint32_t a[4][4];
#pragma unroll
            for (int mi = 0; mi < 4; mi++) {
                uint32_t addr = a_st + ((wm + mi * 16 + arow) * LDHW_ + kb + ak4) * 4;
                ldsm_x4(a[mi][0], a[mi][1], a[mi][2], a[mi][3], addr);
            }
            uint32_t bf[4][2];
#pragma unroll
            for (int np = 0; np < 2; np++) {
                uint32_t addr = b_st + ((wn + np * 16 + brow) * LDHW_ + kb + bk4) * 4;
                ldsm_x4(bf[2 * np][0], bf[2 * np][1],
                        bf[2 * np + 1][0], bf[2 * np + 1][1], addr);
            }
#pragma unroll
            for (int mi = 0; mi < 4; mi++)
#pragma unroll
                for (int ni = 0; ni < 4; ni++)
                    mma_f16_k16(acc[mi][ni], a[mi], bf[ni]);
        }
    };

    const int niter = K / BKH_;
    load_stage(0, 0);
    load_stage(1, 1);

    for (int i = 0; i < niter - 1; i++) {
        asm volatile("cp.async.wait_group 1;\n" ::: "memory");
        __syncthreads();
        if (i + 2 < niter) load_stage((i + 2) % GSTG_, i + 2);
        compute_stage(i % GSTG_);
    }
    asm volatile("cp.async.wait_group 0;\n" ::: "memory");
    __syncthreads();
    compute_stage((niter - 1) % GSTG_);

    float* C = C0;
    int cb = (int)bn;
    if (cb >= Nsplit) { C = C1; cb -= Nsplit; }

#pragma unroll
    for (int mi = 0; mi < 4; mi++) {
        const size_t row = bm + wm + mi * 16 + g;
#pragma unroll
        for (int ni = 0; ni < 4; ni++) {
            const int col = cb + wn + ni * 8 + 2 * tg;
            float* cp0 = C + row * ldc + col;
            float* cp1 = cp0 + (size_t)8 * ldc;
            *(float2*)cp0 = make_float2(acc[mi][ni][0], acc[mi][ni][1]);
            *(float2*)cp1 = make_float2(acc[mi][ni][2], acc[mi][ni][3]);
        }
    }
}

// ---------------- fused RoPE (Q/K) + V transpose/split ----------------------
#define ROPE_TOT_ (NTOK_ * (NH_ + NKV_) * (D_ / 2))
#define VT_TOT_   (B_ * NKV_ * D_ * S_)

__global__ void prep_kernel(const float* __restrict__ cosp,
                            const float* __restrict__ sinp)
{
    int idx = blockIdx.x * blockDim.x + threadIdx.x;
    if (idx < ROPE_TOT_) {
        int d    = idx % (D_ / 2);
        int rest = idx / (D_ / 2);
        int h    = rest % (NH_ + NKV_);
        int tok  = rest / (NH_ + NKV_);

        float c1 = cosp[(size_t)tok * D_ + d];
        float s1 = sinp[(size_t)tok * D_ + d];
        float c2 = cosp[(size_t)tok * D_ + d + D_ / 2];
        float s2 = sinp[(size_t)tok * D_ + d + D_ / 2];

        const float* buf;
        __half *hip, *lop;
        size_t off;
        if (h < NH_) {
            off = (size_t)tok * QDIM_ + h * D_;
            buf = g_q + off; hip = g_qhi + off; lop = g_qlo + off;
        } else {
            off = (size_t)tok * KVDIM_ + (h - NH_) * D_;
            buf = g_k + off; hip = g_khi + off; lop = g_klo + off;
        }

        float x1 = buf[d];
        float x2 = buf[d + D_ / 2];
        float o1 = x1 * c1 - x2 * s1;
        float o2 = x2 * c2 + x1 * s2;

        __half h1v, l1v, h2v, l2v;
        split_f16(o1, h1v, l1v);
        split_f16(o2, h2v, l2v);
        hip[d] = h1v;            lop[d] = l1v;
        hip[d + D_ / 2] = h2v;   lop[d + D_ / 2] = l2v;
    } else {
        int vi = idx - ROPE_TOT_;
        if (vi >= VT_TOT_) return;
        int s    = vi % S_;
        int rest = vi / S_;
        int d    = rest % D_;
        int bkv  = rest / D_;
        int b    = bkv / NKV_;
        int kvh  = bkv % NKV_;
        float x = g_v[((size_t)(b * S_ + s)) * KVDIM_ + kvh * D_ + d];
        __half hi, lo;
        split_f16(x, hi, lo);
        g_vthi[vi] = hi;
        g_vtlo[vi] = lo;
    }
}

// ---------------- block-sparse attention (fp16 planes + ldmatrix) -----------
#define QLDH_  136     // Q/K row stride in halves
#define VLDH_  72      // VT/P row stride in halves
#define QHI_O_ 0
#define QLO_O_ 8704
#define KHI_O_ 17408
#define KLO_O_ 26112
#define VTHI_O_ 34816
#define VTLO_O_ 44032
#define SMH_HALVES_ 53248
#define AT_STAT_FLOATS (128 + 128 + 3 * 64)
#define AT_SMEM_BYTES (SMH_HALVES_ * 2 + AT_STAT_FLOATS * 4)   // 108288

__global__ void __launch_bounds__(256, 2)
attn_kernel()
{
    extern __shared__ __half smh[];
    float* stat = (float*)(smh + SMH_HALVES_);
    float* wmax = stat;
    float* wsum = wmax + 128;
    float* rowm = wsum + 128;
    float* rowl = rowm + 64;
    float* rowf = rowl + 64;
    __shared__ int sel_s[NSEL_];
    __shared__ int keep_s[NSEL_];
    __shared__ int klist[NSEL_];
    __shared__ int kcnt;

    __half* phi = smh + KHI_O_;
    __half* plo = smh + KLO_O_;

    const uint32_t smh_u32 = (uint32_t)__cvta_generic_to_shared(smh);
    const uint32_t qhi_st = smh_u32 + QHI_O_ * 2;
    const uint32_t qlo_st = smh_u32 + QLO_O_ * 2;
    const uint32_t khi_st = smh_u32 + KHI_O_ * 2;
    const uint32_t klo_st = smh_u32 + KLO_O_ * 2;
    const uint32_t vhi_st = smh_u32 + VTHI_O_ * 2;
    const uint32_t vlo_st = smh_u32 + VTLO_O_ * 2;
    const uint32_t phi_st = khi_st;
    const uint32_t plo_st = klo_st;

    const int qid = blockIdx.x;
    const int h   = blockIdx.y;
    const int b   = blockIdx.z;
    const int t   = threadIdx.x;
    const int kvh = h / (NH_ / NKV_);
    const int bkv = b * NKV_ + kvh;

    const int warp = t >> 5, lane = t & 31;
    const int g  = lane >> 2;
    const int tg = lane & 3;
    const int wm  = (warp >> 1) * 16;
    const int nh  = warp & 1;
    const int wn  = nh * 32;
    const int wn2 = nh * 64;
    const int row0 = wm + g;
    const int row1 = wm + g + 8;

    const int arow = lane & 15;
    const int ak8  = (lane >> 4) << 3;
    const int brow = (lane & 7) + ((lane >> 4) << 3);
    const int bk8  = ((lane >> 3) & 1) << 3;

    if (t < NSEL_) {
        int s;
        if (t < NGLOB_) { s = t * STRIDE_; if (s > KB_ - 1) s = KB_ - 1; }
        else            { int j = t - NGLOB_; s = qid - (NLOCAL_ - 1) + j;
                          s = s < 0 ? 0 : (s > KB_ - 1 ? KB_ - 1 : s); }
        bool valid = (s <= qid);
        bool dup = false;
        for (int jj = 0; jj < t; jj++) {
            int sj;
            if (jj < NGLOB_) { sj = jj * STRIDE_; if (sj > KB_ - 1) sj = KB_ - 1; }
            else             { int j2 = jj - NGLOB_; sj = qid - (NLOCAL_ - 1) + j2;
                               sj = sj < 0 ? 0 : (sj > KB_ - 1 ? KB_ - 1 : sj); }
            if (sj == s) dup = true;
        }
        sel_s[t]  = s;
        keep_s[t] = (valid && !dup) ? 1 : 0;
    }
    if (t < 64) { rowm[t] = -1e30f; rowl[t] = 0.0f; }
    __syncthreads();
    if (t == 0) {
        int c = 0;
        for (int j = 0; j < NSEL_; j++)
            if (keep_s[j]) klist[c++] = sel_s[j];
        kcnt = c;
    }
    __syncthreads();
    const int cnt = kcnt;

    auto load_k = [&](int kblk) {
        const __half* shi = g_khi + ((size_t)(b * S_ + kblk * BS_)) * KVDIM_ + kvh * D_;
        const __half* slo = g_klo + ((size_t)(b * S_ + kblk * BS_)) * KVDIM_ + kvh * D_;
#pragma unroll
        for (int j = 0; j < 8; j++) {
            int idx = t + j * 256;
            int pl = idx >> 10, r = (idx >> 4) & 63, c = idx & 15;
            const __half* src = (pl ? slo : shi) + (size_t)r * KVDIM_ + c * 8;
            __half* dstb = smh + (pl ? KLO_O_ : KHI_O_) + r * QLDH_ + c * 8;
            cp_async16((uint32_t)__cvta_generic_to_shared(dstb), src);
        }
        asm volatile("cp.async.commit_group;\n");
    };
    auto load_v = [&](int kblk) {
        const __half* shi = g_vthi + ((size_t)bkv * D_) * S_ + kblk * BS_;
        const __half* slo = g_vtlo + ((size_t)bkv * D_) * S_ + kblk * BS_;
#pragma unroll
        for (int j = 0; j < 8; j++) {
            int idx = t + j * 256;
            int pl = idx >> 10, r = (idx >> 3) & 127, c = idx & 7;
            const __half* src = (pl ? slo : shi) + (size_t)r * S_ + c * 8;
            __half* dstb = smh + (pl ? VTLO_O_ : VTHI_O_) + r * VLDH_ + c * 8;
            cp_async16((uint32_t)__cvta_generic_to_shared(dstb), src);
        }
        asm volatile("cp.async.commit_group;\n");
    };

    load_k(klist[0]);
    {
        const __half* shi = g_qhi + ((size_t)(b * S_ + qid * BS_)) * QDIM_ + h * D_;
        const __half* slo = g_qlo + ((size_t)(b * S_ + qid * BS_)) * QDIM_ + h * D_;
#pragma unroll
        for (int j = 0; j < 8; j++) {
            int idx = t + j * 256;
            int pl = idx >> 10, r = (idx >> 4) & 63, c = idx & 15;
            const __half* src = (pl ? slo : shi) + (size_t)r * QDIM_ + c * 8;
            __half* dstb = smh + (pl ? QLO_O_ : QHI_O_) + r * QLDH_ + c * 8;
            cp_async16((uint32_t)__cvta_generic_to_shared(dstb), src);
        }
        asm volatile("cp.async.commit_group;\n");
    }

    float o[8][4];
#pragma unroll
    for (int ni = 0; ni < 8; ni++)
#pragma unroll
        for (int c = 0; c < 4; c++) o[ni][c] = 0.0f;

    for (int bi = 0; bi < cnt; bi++) {
        const int kblk = klist[bi];
        const bool diag = (kblk == qid);

        asm volatile("cp.async.wait_group 0;\n" ::: "memory");
        __syncthreads();

        load_v(kblk);

        float sacc[4][4];
#pragma unroll
        for (int ni = 0; ni < 4; ni++)
#pragma unroll
            for (int c = 0; c < 4; c++) sacc[ni][c] = 0.0f;

#pragma unroll
        for (int ks = 0; ks < 8; ks++) {
            const int kh = ks * 16;
            uint32_t ah[4], al[4];
            ldsm_x4(ah[0], ah[1], ah[2], ah[3],
                    qhi_st + ((wm + arow) * QLDH_ + kh + ak8) * 2);
            ldsm_x4(al[0], al[1], al[2], al[3],
                    qlo_st + ((wm + arow) * QLDH_ + kh + ak8) * 2);
            uint32_t bh[4][2], bl[4][2];
#pragma unroll
            for (int np = 0; np < 2; np++) {
                ldsm_x4(bh[2 * np][0], bh[2 * np][1], bh[2 * np + 1][0], bh[2 * np + 1][1],
                        khi_st + ((wn + np * 16 + brow) * QLDH_ + kh + bk8) * 2);
                ldsm_x4(bl[2 * np][0], bl[2 * np][1], bl[2 * np + 1][0], bl[2 * np + 1][1],
                        klo_st + ((wn + np * 16 + brow) * QLDH_ + kh + bk8) * 2);
            }
#pragma unroll
            for (int ni = 0; ni < 4; ni++) {
                mma_f16_k16(sacc[ni], ah, bh[ni]);
                mma_f16_k16(sacc[ni], ah, bl[ni]);
                mma_f16_k16(sacc[ni], al, bh[ni]);
            }
        }

        float pm0 = -1e30f, pm1 = -1e30f;
#pragma unroll
        for (int ni = 0; ni < 4; ni++) {
            const int colb = wn + ni * 8 + 2 * tg;
#pragma unroll
            for (int c = 0; c < 4; c++) {
                const int col = colb + (c & 1);
                const int row = (c < 2) ? row0 : row1;
                float v = sacc[ni][c] * SCALE_;
                if (diag && col > row) v += NEG_;
                sacc[ni][c] = v;
                if (c < 2) pm0 = fmaxf(pm0, v);
                else       pm1 = fmaxf(pm1, v);
            }
        }
        pm0 = fmaxf(pm0, __shfl_xor_sync(0xffffffff, pm0, 1));
        pm0 = fmaxf(pm0, __shfl_xor_sync(0xffffffff, pm0, 2));
        pm1 = fmaxf(pm1, __shfl_xor_sync(0xffffffff, pm1, 1));
        pm1 = fmaxf(pm1, __shfl_xor_sync(0xffffffff, pm1, 2));
        if (tg == 0) {
            wmax[nh * 64 + row0] = pm0;
            wmax[nh * 64 + row1] = pm1;
        }
        __syncthreads();

        float mx0 = fmaxf(fmaxf(wmax[row0], wmax[64 + row0]), rowm[row0]);
        float mx1 = fmaxf(fmaxf(wmax[row1], wmax[64 + row1]), rowm[row1]);
        float ps0 = 0.0f, ps1 = 0.0f;
#pragma unroll
        for (int ni = 0; ni < 4; ni++) {
#pragma unroll
            for (int c = 0; c < 4; c++) {
                float p = __expf(sacc[ni][c] - ((c < 2) ? mx0 : mx1));
                sacc[ni][c] = p;
                if (c < 2) ps0 += p; else ps1 += p;
            }
        }
        ps0 += __shfl_xor_sync(0xffffffff, ps0, 1);
        ps0 += __shfl_xor_sync(0xffffffff, ps0, 2);
        ps1 += __shfl_xor_sync(0xffffffff, ps1, 1);
        ps1 += __shfl_xor_sync(0xffffffff, ps1, 2);
        if (tg == 0) {
            wsum[nh * 64 + row0] = ps0;
            wsum[nh * 64 + row1] = ps1;
        }
        float mxt = 0.0f, ft = 0.0f;
        if (t < 64) {
            mxt = fmaxf(fmaxf(wmax[t], wmax[64 + t]), rowm[t]);
            ft  = __expf(rowm[t] - mxt);
            rowf[t] = ft;
        }
        __syncthreads();

        if (t < 64) {
            rowl[t] = rowl[t] * ft + wsum[t] + wsum[64 + t];
            rowm[t] = mxt;
        }

        {
            float f0 = rowf[row0], f1 = rowf[row1];
#pragma unroll
            for (int ni = 0; ni < 8; ni++) {
                o[ni][0] *= f0; o[ni][1] *= f0;
                o[ni][2] *= f1; o[ni][3] *= f1;
            }
        }
#pragma unroll
        for (int ni = 0; ni < 4; ni++) {
            const int colb = wn + ni * 8 + 2 * tg;
            __half h0, l0, h1, l1;
            split_f16(sacc[ni][0], h0, l0);
            split_f16(sacc[ni][1], h1, l1);
            *(__half2*)(phi + row0 * VLDH_ + colb) = __halves2half2(h0, h1);
            *(__half2*)(plo + row0 * VLDH_ + colb) = __halves2half2(l0, l1);
            split_f16(sacc[ni][2], h0, l0);
            split_f16(sacc[ni][3], h1, l1);
            *(__half2*)(phi + row1 * VLDH_ + colb) = __halves2half2(h0, h1);
            *(__half2*)(plo + row1 * VLDH_ + colb) = __halves2half2(l0, l1);
        }

        asm volatile("cp.async.wait_group 0;\n" ::: "memory");
        __syncthreads();

#pragma unroll
        for (int ks = 0; ks < 4; ks++) {
            const int kh = ks * 16;
            uint32_t ah[4], al[4];
            ldsm_x4(ah[0], ah[1], ah[2], ah[3],
                    phi_st + ((wm + arow) * VLDH_ + kh + ak8) * 2);
            ldsm_x4(al[0], al[1], al[2], al[3],
                    plo_st + ((wm + arow) * VLDH_ + kh + ak8) * 2);
            uint32_t bh[8][2], bl[8][2];
#pragma unroll
            for (int np = 0; np < 4; np++) {
                ldsm_x4(bh[2 * np][0], bh[2 * np][1], bh[2 * np + 1][0], bh[2 * np + 1][1],
                        vhi_st + ((wn2 + np * 16 + brow) * VLDH_ + kh + bk8) * 2);
                ldsm_x4(bl[2 * np][0], bl[2 * np][1], bl[2 * np + 1][0], bl[2 * np + 1][1],
                        vlo_st + ((wn2 + np * 16 + brow) * VLDH_ + kh + bk8) * 2);
            }
#pragma unroll
            for (int ni = 0; ni < 8; ni++) {
                mma_f16_k16(o[ni], ah, bh[ni]);
                mma_f16_k16(o[ni], ah, bl[ni]);
                mma_f16_k16(o[ni], al, bh[ni]);
            }
        }
        __syncthreads();

        if (bi + 1 < cnt) load_k(klist[bi + 1]);
    }

    const float invl0 = 1.0f / rowl[row0];
    const float invl1 = 1.0f / rowl[row1];
    __half* ob0 = g_attn + ((size_t)(b * S_ + qid * BS_ + row0)) * QDIM_ + h * D_;
    __half* ob1 = g_attn + ((size_t)(b * S_ + qid * BS_ + row1)) * QDIM_ + h * D_;
#pragma unroll
    for (int ni = 0; ni < 8; ni++) {
        const int col = wn2 + ni * 8 + 2 * tg;
        __half2 h0 = __floats2half2_rn(o[ni][0] * invl0, o[ni][1] * invl0);
        __half2 h1 = __floats2half2_rn(o[ni][2] * invl1, o[ni][3] * invl1);
        *(__half2*)(ob0 + col) = h0;
        *(__half2*)(ob1 + col) = h1;
    }
}

// ---------------- host launcher ---------------------------------------------
extern "C" void kernel_launch(void* const* d_in, const int* in_sizes, int n_in,
                              void* d_out, int out_size)
{
    const float* X    = (const float*)d_in[0];
    const float* cosp = (const float*)d_in[1];
    const float* sinp = (const float*)d_in[2];
    const float* Wq   = (const float*)d_in[3];
    const float* Wk   = (const float*)d_in[4];
    const float* Wv   = (const float*)d_in[5];
    const float* Wo   = (const float*)d_in[6];
    float* out = (float*)d_out;

    float *qb, *kb, *vb;
    __half *ab, *xh, *wh;
    cudaGetSymbolAddress((void**)&qb, g_q);
    cudaGetSymbolAddress((void**)&kb, g_k);
    cudaGetSymbolAddress((void**)&vb, g_v);
    cudaGetSymbolAddress((void**)&ab, g_attn);
    cudaGetSymbolAddress((void**)&xh, g_xh);
    cudaGetSymbolAddress((void**)&wh, g_wh);

    cudaFuncSetAttribute(attn_kernel,
                         cudaFuncAttributeMaxDynamicSharedMemorySize,
                         AT_SMEM_BYTES);
    cudaFuncSetAttribute(gemm_f16_pipe,
                         cudaFuncAttributeMaxDynamicSharedMemorySize,
                         GSMEM_BYTES);

    const int BIG = 1 << 30;

    // one pass: X + all weights -> fp16
    cvt_all_kernel<<<(CVT_TOT4_ + 255) / 256, 256>>>(X, Wq, Wk, Wv, Wo);

    // Q projection: [8192 x 2048]
    gemm_f16_pipe<<<dim3(QDIM_ / 128, NTOK_ / 128), 256, GSMEM_BYTES>>>(
        xh, wh + WQ_OFF_, qb, qb, BIG, QDIM_, H_);

    // fused K+V projection: weights contiguous [1024 x 2048]; split at col 512
    gemm_f16_pipe<<<dim3(2 * KVDIM_ / 128, NTOK_ / 128), 256, GSMEM_BYTES>>>(
        xh, wh + WK_OFF_, kb, vb, KVDIM_, KVDIM_, H_);

    // fused RoPE (Q/K planes) + V transpose/split
    prep_kernel<<<(ROPE_TOT_ + VT_TOT_ + 255) / 256, 256>>>(cosp, sinp);

    // block-sparse attention (fp16 split planes, writes fp16 to g_attn)
    attn_kernel<<<dim3(KB_, NH_, B_), 256, AT_SMEM_BYTES>>>();

    // O projection
    gemm_f16_pipe<<<dim3(H_ / 128, NTOK_ / 128), 256, GSMEM_BYTES>>>(
        ab, wh + WO_OFF_, out, out, BIG, H_, QDIM_);
}